// round 4
// baseline (speedup 1.0000x reference)
#include <cuda_runtime.h>

#define B_   32
#define T_   512
#define D_   512
#define H_   8
#define DK_  64
#define M_   (B_ * T_)   // 16384

// ---- scratch (no allocations allowed) ----
__device__ float g_q[M_ * D_];
__device__ float g_k[M_ * D_];
__device__ float g_v[M_ * D_];
__device__ float g_att[M_ * D_];

// ============================================================================
// C[M,N] = A[M,K] @ W[N,K]^T + bias[N]      (both operands K-contiguous: "NT")
// 64x64 block tile, BK=16, 256 threads, 4x4 per-thread tile.
// Smem tiles stored transposed [BK][BM] so compute reads are contiguous float4.
// ============================================================================
__global__ __launch_bounds__(256) void sgemm_nt_bias(
    const float* __restrict__ A, const float* __restrict__ W,
    const float* __restrict__ bias, float* __restrict__ C,
    int M, int N, int K)
{
    __shared__ float As[16][68];   // [kk][row], pad 68 -> 16B-aligned rows, fewer store conflicts
    __shared__ float Bs[16][68];   // [kk][col]

    const int m0  = blockIdx.y * 64;
    const int n0  = blockIdx.x * 64;
    const int tid = threadIdx.x;
    const int ty  = tid >> 4;          // 0..15 -> rows ty*4..ty*4+3
    const int tx  = tid & 15;          // 0..15 -> cols tx*4..tx*4+3
    const int lr  = tid >> 2;          // load row 0..63
    const int lc  = (tid & 3) << 2;    // load col chunk {0,4,8,12}

    const float* Ap = A + (size_t)(m0 + lr) * K + lc;
    const float* Wp = W + (size_t)(n0 + lr) * K + lc;

    float acc[4][4] = {};

    for (int k0 = 0; k0 < K; k0 += 16) {
        float4 av = *(const float4*)(Ap + k0);
        float4 bv = *(const float4*)(Wp + k0);
        As[lc + 0][lr] = av.x; As[lc + 1][lr] = av.y;
        As[lc + 2][lr] = av.z; As[lc + 3][lr] = av.w;
        Bs[lc + 0][lr] = bv.x; Bs[lc + 1][lr] = bv.y;
        Bs[lc + 2][lr] = bv.z; Bs[lc + 3][lr] = bv.w;
        __syncthreads();

        #pragma unroll
        for (int kk = 0; kk < 16; kk++) {
            float4 a4 = *(const float4*)&As[kk][ty * 4];
            float4 b4 = *(const float4*)&Bs[kk][tx * 4];
            float a[4] = {a4.x, a4.y, a4.z, a4.w};
            float b[4] = {b4.x, b4.y, b4.z, b4.w};
            #pragma unroll
            for (int i = 0; i < 4; i++)
                #pragma unroll
                for (int j = 0; j < 4; j++)
                    acc[i][j] = fmaf(a[i], b[j], acc[i][j]);
        }
        __syncthreads();
    }

    float4 bb = *(const float4*)(bias + n0 + tx * 4);
    float bj[4] = {bb.x, bb.y, bb.z, bb.w};
    #pragma unroll
    for (int i = 0; i < 4; i++) {
        float4 o;
        o.x = acc[i][0] + bj[0]; o.y = acc[i][1] + bj[1];
        o.z = acc[i][2] + bj[2]; o.w = acc[i][3] + bj[3];
        *(float4*)(C + (size_t)(m0 + ty * 4 + i) * N + n0 + tx * 4) = o;
    }
}

// ============================================================================
// Flash attention with relative-position bias + key padding mask.
// Block = 64 queries of one (b,h). 8 K/V tiles of 64 keys, online softmax.
// Smem: Qt (transposed), KP (K transposed, later aliased by P transposed),
//       Vs (row-major). 3 * 64*64 * 4B = 48KB exactly (static limit).
// ============================================================================
__global__ __launch_bounds__(256) void attn_kernel(
    const float* __restrict__ Q, const float* __restrict__ Kg,
    const float* __restrict__ Vg,
    const float* __restrict__ rel,           // [1023, 8]
    const unsigned int* __restrict__ kpm,    // [B, T], nonzero word => masked
    float* __restrict__ out)                 // [B, T, H, DK]
{
    __shared__ float Qt[64 * 64];   // Qt[d*64 + r]
    __shared__ float KP[64 * 64];   // Kt[d*64 + c]  then  Pt[k*64 + r]
    __shared__ float Vs[64 * 64];   // Vs[k*64 + d]

    const int bh = blockIdx.y;
    const int b  = bh >> 3;
    const int h  = bh & 7;
    const int q0 = blockIdx.x * 64;
    const int tid = threadIdx.x;
    const int ty = tid >> 4;       // row group
    const int tx = tid & 15;       // col group
    const int ldr = tid >> 4;      // loader: row base
    const int ldc = (tid & 15) * 4;

    // ---- load Q tile transposed ----
    {
        const float* qg = Q + ((size_t)(b * T_ + q0)) * D_ + h * DK_;
        #pragma unroll
        for (int rep = 0; rep < 4; rep++) {
            int r = ldr + rep * 16;
            float4 v = *(const float4*)(qg + (size_t)r * D_ + ldc);
            Qt[(ldc + 0) * 64 + r] = v.x;
            Qt[(ldc + 1) * 64 + r] = v.y;
            Qt[(ldc + 2) * 64 + r] = v.z;
            Qt[(ldc + 3) * 64 + r] = v.w;
        }
    }

    float m[4], l[4], o[4][4];
    #pragma unroll
    for (int i = 0; i < 4; i++) {
        m[i] = -1e30f; l[i] = 0.f;
        #pragma unroll
        for (int j = 0; j < 4; j++) o[i][j] = 0.f;
    }

    for (int kt = 0; kt < 8; kt++) {
        const int k0 = kt * 64;
        __syncthreads();   // prior PV reads of KP/Vs done (also covers Qt store on kt=0... see next sync)

        // ---- load K tile (transposed) and V tile ----
        const float* kg = Kg + ((size_t)(b * T_ + k0)) * D_ + h * DK_;
        const float* vg = Vg + ((size_t)(b * T_ + k0)) * D_ + h * DK_;
        #pragma unroll
        for (int rep = 0; rep < 4; rep++) {
            int r = ldr + rep * 16;
            float4 kv = *(const float4*)(kg + (size_t)r * D_ + ldc);
            KP[(ldc + 0) * 64 + r] = kv.x;
            KP[(ldc + 1) * 64 + r] = kv.y;
            KP[(ldc + 2) * 64 + r] = kv.z;
            KP[(ldc + 3) * 64 + r] = kv.w;
            float4 vv = *(const float4*)(vg + (size_t)r * D_ + ldc);
            *(float4*)&Vs[r * 64 + ldc] = vv;
        }
        __syncthreads();

        // ---- S = Q K^T ----
        float s[4][4] = {};
        #pragma unroll 16
        for (int d = 0; d < 64; d++) {
            float4 a4 = *(const float4*)&Qt[d * 64 + ty * 4];
            float4 b4 = *(const float4*)&KP[d * 64 + tx * 4];
            float a[4] = {a4.x, a4.y, a4.z, a4.w};
            float bb[4] = {b4.x, b4.y, b4.z, b4.w};
            #pragma unroll
            for (int i = 0; i < 4; i++)
                #pragma unroll
                for (int j = 0; j < 4; j++)
                    s[i][j] = fmaf(a[i], bb[j], s[i][j]);
        }
        __syncthreads();   // all threads done reading KP before Pt overwrite

        // ---- scale + rel-pos bias + mask ----
        // bias index: (k_abs - q_abs + 511)*8 + h ; distinct diffs j-i in [-3,3]
        const int base = (k0 + tx * 4 - q0 - ty * 4 + 511) * 8 + h;
        float r7[7];
        #pragma unroll
        for (int u = 0; u < 7; u++) r7[u] = __ldg(&rel[base + (u - 3) * 8]);
        float madd[4];
        #pragma unroll
        for (int j = 0; j < 4; j++)
            madd[j] = __ldg(&kpm[b * T_ + k0 + tx * 4 + j]) ? -2e30f : 0.f;

        #pragma unroll
        for (int i = 0; i < 4; i++)
            #pragma unroll
            for (int j = 0; j < 4; j++)
                s[i][j] = fmaf(s[i][j], 0.125f, r7[j - i + 3] + madd[j]);

        // ---- online softmax (row stats replicated over the 16 tx lanes) ----
        #pragma unroll
        for (int i = 0; i < 4; i++) {
            float rm = fmaxf(fmaxf(s[i][0], s[i][1]), fmaxf(s[i][2], s[i][3]));
            #pragma unroll
            for (int off = 8; off >= 1; off >>= 1)
                rm = fmaxf(rm, __shfl_xor_sync(0xffffffffu, rm, off));
            float mn = fmaxf(m[i], rm);
            float alpha = __expf(m[i] - mn);
            m[i] = mn;
            float rs = 0.f;
            #pragma unroll
            for (int j = 0; j < 4; j++) {
                float p = __expf(s[i][j] - mn);
                s[i][j] = p;
                rs += p;
            }
            #pragma unroll
            for (int off = 8; off >= 1; off >>= 1)
                rs += __shfl_xor_sync(0xffffffffu, rs, off);
            l[i] = l[i] * alpha + rs;
            #pragma unroll
            for (int j = 0; j < 4; j++) o[i][j] *= alpha;
        }

        // ---- write P transposed into KP ----
        #pragma unroll
        for (int i = 0; i < 4; i++)
            #pragma unroll
            for (int j = 0; j < 4; j++)
                KP[(tx * 4 + j) * 64 + (ty * 4 + i)] = s[i][j];
        __syncthreads();

        // ---- O += P V ----
        #pragma unroll 16
        for (int k = 0; k < 64; k++) {
            float4 a4 = *(const float4*)&KP[k * 64 + ty * 4];
            float4 b4 = *(const float4*)&Vs[k * 64 + tx * 4];
            float a[4] = {a4.x, a4.y, a4.z, a4.w};
            float bb[4] = {b4.x, b4.y, b4.z, b4.w};
            #pragma unroll
            for (int i = 0; i < 4; i++)
                #pragma unroll
                for (int j = 0; j < 4; j++)
                    o[i][j] = fmaf(a[i], bb[j], o[i][j]);
        }
    }

    // ---- epilogue: normalize and store ----
    #pragma unroll
    for (int i = 0; i < 4; i++) {
        float inv = 1.f / l[i];
        float4 ov;
        ov.x = o[i][0] * inv; ov.y = o[i][1] * inv;
        ov.z = o[i][2] * inv; ov.w = o[i][3] * inv;
        *(float4*)(out + ((size_t)(b * T_ + q0 + ty * 4 + i)) * D_ + h * DK_ + tx * 4) = ov;
    }
}

// ============================================================================
extern "C" void kernel_launch(void* const* d_in, const int* in_sizes, int n_in,
                              void* d_out, int out_size)
{
    const float* x   = (const float*)d_in[0];
    const float* Wq  = (const float*)d_in[1];
    const float* bq  = (const float*)d_in[2];
    const float* Wk  = (const float*)d_in[3];
    const float* bk  = (const float*)d_in[4];
    const float* Wv  = (const float*)d_in[5];
    const float* bv  = (const float*)d_in[6];
    const float* Wo  = (const float*)d_in[7];
    const float* bo  = (const float*)d_in[8];
    const float* rel = (const float*)d_in[9];
    const unsigned int* kpm = (const unsigned int*)d_in[10];
    float* out = (float*)d_out;

    float *qp, *kp, *vp, *ap;
    cudaGetSymbolAddress((void**)&qp, g_q);
    cudaGetSymbolAddress((void**)&kp, g_k);
    cudaGetSymbolAddress((void**)&vp, g_v);
    cudaGetSymbolAddress((void**)&ap, g_att);

    dim3 gemm_grid(D_ / 64, M_ / 64);   // (8, 256)
    sgemm_nt_bias<<<gemm_grid, 256>>>(x, Wq, bq, qp, M_, D_, D_);
    sgemm_nt_bias<<<gemm_grid, 256>>>(x, Wk, bk, kp, M_, D_, D_);
    sgemm_nt_bias<<<gemm_grid, 256>>>(x, Wv, bv, vp, M_, D_, D_);

    dim3 at_grid(T_ / 64, B_ * H_);     // (8, 256)
    attn_kernel<<<at_grid, 256>>>(qp, kp, vp, rel, kpm, ap);

    sgemm_nt_bias<<<gemm_grid, 256>>>(ap, Wo, bo, out, M_, D_, D_);
}

// round 5
// speedup vs baseline: 1.0853x; 1.0853x over previous
#include <cuda_runtime.h>

#define B_   32
#define T_   512
#define D_   512
#define H_   8
#define DK_  64
#define M_   (B_ * T_)   // 16384

// ---- scratch (no allocations allowed) ----
__device__ float g_q[M_ * D_];
__device__ float g_k[M_ * D_];
__device__ float g_v[M_ * D_];
__device__ float g_att[M_ * D_];

// ============================================================================
// C[M,N] = A[M,K] @ W[N,K]^T + bias[N]      (both operands K-contiguous: "NT")
// 64x64 block tile, BK=16, 256 threads, 4x4 per-thread tile.
// Smem tiles stored transposed [BK][BM] so compute reads are contiguous float4.
// ============================================================================
__global__ __launch_bounds__(256) void sgemm_nt_bias(
    const float* __restrict__ A, const float* __restrict__ W,
    const float* __restrict__ bias, float* __restrict__ C,
    int M, int N, int K)
{
    __shared__ float As[16][68];   // [kk][row], pad 68 -> 16B-aligned rows, fewer store conflicts
    __shared__ float Bs[16][68];   // [kk][col]

    const int m0  = blockIdx.y * 64;
    const int n0  = blockIdx.x * 64;
    const int tid = threadIdx.x;
    const int ty  = tid >> 4;          // 0..15 -> rows ty*4..ty*4+3
    const int tx  = tid & 15;          // 0..15 -> cols tx*4..tx*4+3
    const int lr  = tid >> 2;          // load row 0..63
    const int lc  = (tid & 3) << 2;    // load col chunk {0,4,8,12}

    const float* Ap = A + (size_t)(m0 + lr) * K + lc;
    const float* Wp = W + (size_t)(n0 + lr) * K + lc;

    float acc[4][4] = {};

    for (int k0 = 0; k0 < K; k0 += 16) {
        float4 av = *(const float4*)(Ap + k0);
        float4 bv = *(const float4*)(Wp + k0);
        As[lc + 0][lr] = av.x; As[lc + 1][lr] = av.y;
        As[lc + 2][lr] = av.z; As[lc + 3][lr] = av.w;
        Bs[lc + 0][lr] = bv.x; Bs[lc + 1][lr] = bv.y;
        Bs[lc + 2][lr] = bv.z; Bs[lc + 3][lr] = bv.w;
        __syncthreads();

        #pragma unroll
        for (int kk = 0; kk < 16; kk++) {
            float4 a4 = *(const float4*)&As[kk][ty * 4];
            float4 b4 = *(const float4*)&Bs[kk][tx * 4];
            float a[4] = {a4.x, a4.y, a4.z, a4.w};
            float b[4] = {b4.x, b4.y, b4.z, b4.w};
            #pragma unroll
            for (int i = 0; i < 4; i++)
                #pragma unroll
                for (int j = 0; j < 4; j++)
                    acc[i][j] = fmaf(a[i], b[j], acc[i][j]);
        }
        __syncthreads();
    }

    float4 bb = *(const float4*)(bias + n0 + tx * 4);
    float bj[4] = {bb.x, bb.y, bb.z, bb.w};
    #pragma unroll
    for (int i = 0; i < 4; i++) {
        float4 o;
        o.x = acc[i][0] + bj[0]; o.y = acc[i][1] + bj[1];
        o.z = acc[i][2] + bj[2]; o.w = acc[i][3] + bj[3];
        *(float4*)(C + (size_t)(m0 + ty * 4 + i) * N + n0 + tx * 4) = o;
    }
}

// ============================================================================
// Flash attention with relative-position bias + key padding mask.
// Block = 64 queries of one (b,h). 8 K/V tiles of 64 keys, online softmax.
// Smem: Qt (transposed), KP (K transposed, later aliased by P transposed),
//       Vs (row-major). 3 * 64*64 * 4B = 48KB exactly (static limit).
// ============================================================================
__global__ __launch_bounds__(256) void attn_kernel(
    const float* __restrict__ Q, const float* __restrict__ Kg,
    const float* __restrict__ Vg,
    const float* __restrict__ rel,           // [1023, 8]
    const unsigned int* __restrict__ kpm,    // [B, T], nonzero word => masked
    float* __restrict__ out)                 // [B, T, H, DK]
{
    __shared__ float Qt[64 * 64];   // Qt[d*64 + r]
    __shared__ float KP[64 * 64];   // Kt[d*64 + c]  then  Pt[k*64 + r]
    __shared__ float Vs[64 * 64];   // Vs[k*64 + d]

    const int bh = blockIdx.y;
    const int b  = bh >> 3;
    const int h  = bh & 7;
    const int q0 = blockIdx.x * 64;
    const int tid = threadIdx.x;
    const int ty = tid >> 4;       // row group
    const int tx = tid & 15;       // col group
    const int ldr = tid >> 4;      // loader: row base
    const int ldc = (tid & 15) * 4;

    // ---- load Q tile transposed ----
    {
        const float* qg = Q + ((size_t)(b * T_ + q0)) * D_ + h * DK_;
        #pragma unroll
        for (int rep = 0; rep < 4; rep++) {
            int r = ldr + rep * 16;
            float4 v = *(const float4*)(qg + (size_t)r * D_ + ldc);
            Qt[(ldc + 0) * 64 + r] = v.x;
            Qt[(ldc + 1) * 64 + r] = v.y;
            Qt[(ldc + 2) * 64 + r] = v.z;
            Qt[(ldc + 3) * 64 + r] = v.w;
        }
    }

    float m[4], l[4], o[4][4];
    #pragma unroll
    for (int i = 0; i < 4; i++) {
        m[i] = -1e30f; l[i] = 0.f;
        #pragma unroll
        for (int j = 0; j < 4; j++) o[i][j] = 0.f;
    }

    for (int kt = 0; kt < 8; kt++) {
        const int k0 = kt * 64;
        __syncthreads();   // prior PV reads of KP/Vs done (also covers Qt store on kt=0... see next sync)

        // ---- load K tile (transposed) and V tile ----
        const float* kg = Kg + ((size_t)(b * T_ + k0)) * D_ + h * DK_;
        const float* vg = Vg + ((size_t)(b * T_ + k0)) * D_ + h * DK_;
        #pragma unroll
        for (int rep = 0; rep < 4; rep++) {
            int r = ldr + rep * 16;
            float4 kv = *(const float4*)(kg + (size_t)r * D_ + ldc);
            KP[(ldc + 0) * 64 + r] = kv.x;
            KP[(ldc + 1) * 64 + r] = kv.y;
            KP[(ldc + 2) * 64 + r] = kv.z;
            KP[(ldc + 3) * 64 + r] = kv.w;
            float4 vv = *(const float4*)(vg + (size_t)r * D_ + ldc);
            *(float4*)&Vs[r * 64 + ldc] = vv;
        }
        __syncthreads();

        // ---- S = Q K^T ----
        float s[4][4] = {};
        #pragma unroll 16
        for (int d = 0; d < 64; d++) {
            float4 a4 = *(const float4*)&Qt[d * 64 + ty * 4];
            float4 b4 = *(const float4*)&KP[d * 64 + tx * 4];
            float a[4] = {a4.x, a4.y, a4.z, a4.w};
            float bb[4] = {b4.x, b4.y, b4.z, b4.w};
            #pragma unroll
            for (int i = 0; i < 4; i++)
                #pragma unroll
                for (int j = 0; j < 4; j++)
                    s[i][j] = fmaf(a[i], bb[j], s[i][j]);
        }
        __syncthreads();   // all threads done reading KP before Pt overwrite

        // ---- scale + rel-pos bias + mask ----
        // bias index: (k_abs - q_abs + 511)*8 + h ; distinct diffs j-i in [-3,3]
        const int base = (k0 + tx * 4 - q0 - ty * 4 + 511) * 8 + h;
        float r7[7];
        #pragma unroll
        for (int u = 0; u < 7; u++) r7[u] = __ldg(&rel[base + (u - 3) * 8]);
        float madd[4];
        #pragma unroll
        for (int j = 0; j < 4; j++)
            madd[j] = __ldg(&kpm[b * T_ + k0 + tx * 4 + j]) ? -2e30f : 0.f;

        #pragma unroll
        for (int i = 0; i < 4; i++)
            #pragma unroll
            for (int j = 0; j < 4; j++)
                s[i][j] = fmaf(s[i][j], 0.125f, r7[j - i + 3] + madd[j]);

        // ---- online softmax (row stats replicated over the 16 tx lanes) ----
        #pragma unroll
        for (int i = 0; i < 4; i++) {
            float rm = fmaxf(fmaxf(s[i][0], s[i][1]), fmaxf(s[i][2], s[i][3]));
            #pragma unroll
            for (int off = 8; off >= 1; off >>= 1)
                rm = fmaxf(rm, __shfl_xor_sync(0xffffffffu, rm, off));
            float mn = fmaxf(m[i], rm);
            float alpha = __expf(m[i] - mn);
            m[i] = mn;
            float rs = 0.f;
            #pragma unroll
            for (int j = 0; j < 4; j++) {
                float p = __expf(s[i][j] - mn);
                s[i][j] = p;
                rs += p;
            }
            #pragma unroll
            for (int off = 8; off >= 1; off >>= 1)
                rs += __shfl_xor_sync(0xffffffffu, rs, off);
            l[i] = l[i] * alpha + rs;
            #pragma unroll
            for (int j = 0; j < 4; j++) o[i][j] *= alpha;
        }

        // ---- write P transposed into KP ----
        #pragma unroll
        for (int i = 0; i < 4; i++)
            #pragma unroll
            for (int j = 0; j < 4; j++)
                KP[(tx * 4 + j) * 64 + (ty * 4 + i)] = s[i][j];
        __syncthreads();

        // ---- O += P V ----
        #pragma unroll 16
        for (int k = 0; k < 64; k++) {
            float4 a4 = *(const float4*)&KP[k * 64 + ty * 4];
            float4 b4 = *(const float4*)&Vs[k * 64 + tx * 4];
            float a[4] = {a4.x, a4.y, a4.z, a4.w};
            float bb[4] = {b4.x, b4.y, b4.z, b4.w};
            #pragma unroll
            for (int i = 0; i < 4; i++)
                #pragma unroll
                for (int j = 0; j < 4; j++)
                    o[i][j] = fmaf(a[i], bb[j], o[i][j]);
        }
    }

    // ---- epilogue: normalize and store ----
    #pragma unroll
    for (int i = 0; i < 4; i++) {
        float inv = 1.f / l[i];
        float4 ov;
        ov.x = o[i][0] * inv; ov.y = o[i][1] * inv;
        ov.z = o[i][2] * inv; ov.w = o[i][3] * inv;
        *(float4*)(out + ((size_t)(b * T_ + q0 + ty * 4 + i)) * D_ + h * DK_ + tx * 4) = ov;
    }
}

// ============================================================================
extern "C" void kernel_launch(void* const* d_in, const int* in_sizes, int n_in,
                              void* d_out, int out_size)
{
    const float* x   = (const float*)d_in[0];
    const float* Wq  = (const float*)d_in[1];
    const float* bq  = (const float*)d_in[2];
    const float* Wk  = (const float*)d_in[3];
    const float* bk  = (const float*)d_in[4];
    const float* Wv  = (const float*)d_in[5];
    const float* bv  = (const float*)d_in[6];
    const float* Wo  = (const float*)d_in[7];
    const float* bo  = (const float*)d_in[8];
    const float* rel = (const float*)d_in[9];
    const unsigned int* kpm = (const unsigned int*)d_in[10];
    float* out = (float*)d_out;

    float *qp, *kp, *vp, *ap;
    cudaGetSymbolAddress((void**)&qp, g_q);
    cudaGetSymbolAddress((void**)&kp, g_k);
    cudaGetSymbolAddress((void**)&vp, g_v);
    cudaGetSymbolAddress((void**)&ap, g_att);

    dim3 gemm_grid(D_ / 64, M_ / 64);   // (8, 256)
    sgemm_nt_bias<<<gemm_grid, 256>>>(x, Wq, bq, qp, M_, D_, D_);
    sgemm_nt_bias<<<gemm_grid, 256>>>(x, Wk, bk, kp, M_, D_, D_);
    sgemm_nt_bias<<<gemm_grid, 256>>>(x, Wv, bv, vp, M_, D_, D_);

    dim3 at_grid(T_ / 64, B_ * H_);     // (8, 256)
    attn_kernel<<<at_grid, 256>>>(qp, kp, vp, rel, kpm, ap);

    sgemm_nt_bias<<<gemm_grid, 256>>>(ap, Wo, bo, out, M_, D_, D_);
}

// round 6
// speedup vs baseline: 1.2243x; 1.1281x over previous
#include <cuda_runtime.h>

#define B_   32
#define T_   512
#define D_   512
#define H_   8
#define DK_  64
#define M_   (B_ * T_)   // 16384

// ---- scratch (no allocations allowed) ----
__device__ float g_q[M_ * D_];
__device__ float g_k[M_ * D_];
__device__ float g_v[M_ * D_];
__device__ float g_att[M_ * D_];

// ============================================================================
// C[M,N] = A[M,K] @ W[N,K]^T + bias[N]   (NT, K-contiguous both sides)
// 64x64 block tile, BK=16, 256 threads, 4x4 per-thread tile. (measured ~90%
// of fp32 FFMA roofline -- unchanged this round)
// ============================================================================
__device__ __forceinline__ void sgemm_body(
    const float* __restrict__ A, const float* __restrict__ W,
    const float* __restrict__ bias, float* __restrict__ C,
    int M, int N, int K)
{
    __shared__ float As[16][68];
    __shared__ float Bs[16][68];

    const int m0  = blockIdx.y * 64;
    const int n0  = blockIdx.x * 64;
    const int tid = threadIdx.x;
    const int ty  = tid >> 4;
    const int tx  = tid & 15;
    const int lr  = tid >> 2;
    const int lc  = (tid & 3) << 2;

    const float* Ap = A + (size_t)(m0 + lr) * K + lc;
    const float* Wp = W + (size_t)(n0 + lr) * K + lc;

    float acc[4][4] = {};

    for (int k0 = 0; k0 < K; k0 += 16) {
        float4 av = *(const float4*)(Ap + k0);
        float4 bv = *(const float4*)(Wp + k0);
        As[lc + 0][lr] = av.x; As[lc + 1][lr] = av.y;
        As[lc + 2][lr] = av.z; As[lc + 3][lr] = av.w;
        Bs[lc + 0][lr] = bv.x; Bs[lc + 1][lr] = bv.y;
        Bs[lc + 2][lr] = bv.z; Bs[lc + 3][lr] = bv.w;
        __syncthreads();

        #pragma unroll
        for (int kk = 0; kk < 16; kk++) {
            float4 a4 = *(const float4*)&As[kk][ty * 4];
            float4 b4 = *(const float4*)&Bs[kk][tx * 4];
            float a[4] = {a4.x, a4.y, a4.z, a4.w};
            float b[4] = {b4.x, b4.y, b4.z, b4.w};
            #pragma unroll
            for (int i = 0; i < 4; i++)
                #pragma unroll
                for (int j = 0; j < 4; j++)
                    acc[i][j] = fmaf(a[i], b[j], acc[i][j]);
        }
        __syncthreads();
    }

    float4 bb = *(const float4*)(bias + n0 + tx * 4);
    float bj[4] = {bb.x, bb.y, bb.z, bb.w};
    #pragma unroll
    for (int i = 0; i < 4; i++) {
        float4 o;
        o.x = acc[i][0] + bj[0]; o.y = acc[i][1] + bj[1];
        o.z = acc[i][2] + bj[2]; o.w = acc[i][3] + bj[3];
        *(float4*)(C + (size_t)(m0 + ty * 4 + i) * N + n0 + tx * 4) = o;
    }
}

// Fused Q/K/V projection: blockIdx.z selects the weight/bias/output set.
__global__ __launch_bounds__(256) void qkv_gemm(
    const float* __restrict__ A,
    const float* __restrict__ Wq, const float* __restrict__ bq,
    const float* __restrict__ Wk, const float* __restrict__ bk,
    const float* __restrict__ Wv, const float* __restrict__ bv,
    float* __restrict__ Cq, float* __restrict__ Ck, float* __restrict__ Cv)
{
    const int z = blockIdx.z;
    const float* W    = (z == 0) ? Wq : (z == 1) ? Wk : Wv;
    const float* bias = (z == 0) ? bq : (z == 1) ? bk : bv;
    float*       C    = (z == 0) ? Cq : (z == 1) ? Ck : Cv;
    sgemm_body(A, W, bias, C, M_, D_, D_);
}

__global__ __launch_bounds__(256) void out_gemm(
    const float* __restrict__ A, const float* __restrict__ W,
    const float* __restrict__ bias, float* __restrict__ C)
{
    sgemm_body(A, W, bias, C, M_, D_, D_);
}

// ============================================================================
// Flash attention, 64 queries/block, 8 key tiles of 64, online softmax.
// Transposed tiles (Qt, Kt, Pt) use an XOR swizzle on the token index:
//   addr(d, t) = d*64 + (((t>>2) ^ (d>>2)) & 15)*4 + (t&3)
// -> compute-side float4 reads remain aligned + conflict-free,
// -> transpose scatter stores drop from 16-way to 2-way,
// -> P store becomes a conflict-light float4 store.
// Vs stays row-major (already conflict-free). Smem = 48KB static.
// ============================================================================
#define SWZ(d, t) (((d) << 6) + (((((t) >> 2) ^ ((d) >> 2)) & 15) << 2) + ((t) & 3))
// float4-aligned variant for t = tg*4 (t&3 == 0):
#define SWZ4(d, tg) (((d) << 6) + ((((tg) ^ ((d) >> 2)) & 15) << 2))

__global__ __launch_bounds__(256) void attn_kernel(
    const float* __restrict__ Q, const float* __restrict__ Kg,
    const float* __restrict__ Vg,
    const float* __restrict__ rel,           // [1023, 8]
    const unsigned int* __restrict__ kpm,    // [B, T], nonzero word => masked
    float* __restrict__ out)                 // [B, T, H, DK]
{
    __shared__ __align__(16) float Qt[64 * 64];   // swizzled [d][token]
    __shared__ __align__(16) float KP[64 * 64];   // swizzled Kt [d][tok], then Pt [k][row]
    __shared__ __align__(16) float Vs[64 * 64];   // row-major [tok][d]

    const int bh = blockIdx.y;
    const int b  = bh >> 3;
    const int h  = bh & 7;
    const int q0 = blockIdx.x * 64;
    const int tid = threadIdx.x;
    const int ty = tid >> 4;       // 0..15 -> rows ty*4..+3
    const int tx = tid & 15;       // 0..15 -> cols tx*4..+3
    const int ldr = tid >> 4;
    const int ldc = (tid & 15) * 4;

    // ---- load Q tile transposed + swizzled ----
    {
        const float* qg = Q + ((size_t)(b * T_ + q0)) * D_ + h * DK_;
        #pragma unroll
        for (int rep = 0; rep < 4; rep++) {
            int r = ldr + rep * 16;
            float4 v = *(const float4*)(qg + (size_t)r * D_ + ldc);
            Qt[SWZ(ldc + 0, r)] = v.x;
            Qt[SWZ(ldc + 1, r)] = v.y;
            Qt[SWZ(ldc + 2, r)] = v.z;
            Qt[SWZ(ldc + 3, r)] = v.w;
        }
    }

    float m[4], l[4], o[4][4];
    #pragma unroll
    for (int i = 0; i < 4; i++) {
        m[i] = -1e30f; l[i] = 0.f;
        #pragma unroll
        for (int j = 0; j < 4; j++) o[i][j] = 0.f;
    }

    for (int kt = 0; kt < 8; kt++) {
        const int k0 = kt * 64;
        __syncthreads();   // prior PV reads of KP/Vs done (kt=0: Qt stores visible after next sync)

        // ---- load K tile (transposed+swizzled) and V tile (row-major) ----
        const float* kg = Kg + ((size_t)(b * T_ + k0)) * D_ + h * DK_;
        const float* vg = Vg + ((size_t)(b * T_ + k0)) * D_ + h * DK_;
        #pragma unroll
        for (int rep = 0; rep < 4; rep++) {
            int r = ldr + rep * 16;
            float4 kv = *(const float4*)(kg + (size_t)r * D_ + ldc);
            KP[SWZ(ldc + 0, r)] = kv.x;
            KP[SWZ(ldc + 1, r)] = kv.y;
            KP[SWZ(ldc + 2, r)] = kv.z;
            KP[SWZ(ldc + 3, r)] = kv.w;
            float4 vv = *(const float4*)(vg + (size_t)r * D_ + ldc);
            *(float4*)&Vs[r * 64 + ldc] = vv;
        }
        __syncthreads();

        // ---- S = Q K^T ----
        float s[4][4] = {};
        #pragma unroll 16
        for (int d = 0; d < 64; d++) {
            float4 a4 = *(const float4*)&Qt[SWZ4(d, ty)];
            float4 b4 = *(const float4*)&KP[SWZ4(d, tx)];
            float a[4] = {a4.x, a4.y, a4.z, a4.w};
            float bb[4] = {b4.x, b4.y, b4.z, b4.w};
            #pragma unroll
            for (int i = 0; i < 4; i++)
                #pragma unroll
                for (int j = 0; j < 4; j++)
                    s[i][j] = fmaf(a[i], bb[j], s[i][j]);
        }
        __syncthreads();   // all threads done reading KP before Pt overwrite

        // ---- scale + rel-pos bias + mask ----
        const int base = (k0 + tx * 4 - q0 - ty * 4 + 511) * 8 + h;
        float r7[7];
        #pragma unroll
        for (int u = 0; u < 7; u++) r7[u] = __ldg(&rel[base + (u - 3) * 8]);
        uint4 mw = *(const uint4*)&kpm[b * T_ + k0 + tx * 4];
        float madd[4];
        madd[0] = mw.x ? -2e30f : 0.f;
        madd[1] = mw.y ? -2e30f : 0.f;
        madd[2] = mw.z ? -2e30f : 0.f;
        madd[3] = mw.w ? -2e30f : 0.f;

        #pragma unroll
        for (int i = 0; i < 4; i++)
            #pragma unroll
            for (int j = 0; j < 4; j++)
                s[i][j] = fmaf(s[i][j], 0.125f, r7[j - i + 3] + madd[j]);

        // ---- online softmax (row stats replicated over the 16 tx lanes) ----
        #pragma unroll
        for (int i = 0; i < 4; i++) {
            float rm = fmaxf(fmaxf(s[i][0], s[i][1]), fmaxf(s[i][2], s[i][3]));
            #pragma unroll
            for (int off = 8; off >= 1; off >>= 1)
                rm = fmaxf(rm, __shfl_xor_sync(0xffffffffu, rm, off));
            float mn = fmaxf(m[i], rm);
            float alpha = __expf(m[i] - mn);
            m[i] = mn;
            float rs = 0.f;
            #pragma unroll
            for (int j = 0; j < 4; j++) {
                float p = __expf(s[i][j] - mn);
                s[i][j] = p;
                rs += p;
            }
            #pragma unroll
            for (int off = 8; off >= 1; off >>= 1)
                rs += __shfl_xor_sync(0xffffffffu, rs, off);
            l[i] = l[i] * alpha + rs;
            #pragma unroll
            for (int j = 0; j < 4; j++) o[i][j] *= alpha;
        }

        // ---- write P transposed into KP (float4 over the row index i) ----
        #pragma unroll
        for (int j = 0; j < 4; j++) {
            float4 pv;
            pv.x = s[0][j]; pv.y = s[1][j]; pv.z = s[2][j]; pv.w = s[3][j];
            *(float4*)&KP[SWZ4(tx * 4 + j, ty)] = pv;
        }
        __syncthreads();

        // ---- O += P V ----
        #pragma unroll 16
        for (int k = 0; k < 64; k++) {
            float4 a4 = *(const float4*)&KP[SWZ4(k, ty)];
            float4 b4 = *(const float4*)&Vs[k * 64 + tx * 4];
            float a[4] = {a4.x, a4.y, a4.z, a4.w};
            float bb[4] = {b4.x, b4.y, b4.z, b4.w};
            #pragma unroll
            for (int i = 0; i < 4; i++)
                #pragma unroll
                for (int j = 0; j < 4; j++)
                    o[i][j] = fmaf(a[i], bb[j], o[i][j]);
        }
    }

    // ---- epilogue: normalize and store ----
    #pragma unroll
    for (int i = 0; i < 4; i++) {
        float inv = 1.f / l[i];
        float4 ov;
        ov.x = o[i][0] * inv; ov.y = o[i][1] * inv;
        ov.z = o[i][2] * inv; ov.w = o[i][3] * inv;
        *(float4*)(out + ((size_t)(b * T_ + q0 + ty * 4 + i)) * D_ + h * DK_ + tx * 4) = ov;
    }
}

// ============================================================================
extern "C" void kernel_launch(void* const* d_in, const int* in_sizes, int n_in,
                              void* d_out, int out_size)
{
    const float* x   = (const float*)d_in[0];
    const float* Wq  = (const float*)d_in[1];
    const float* bq  = (const float*)d_in[2];
    const float* Wk  = (const float*)d_in[3];
    const float* bk  = (const float*)d_in[4];
    const float* Wv  = (const float*)d_in[5];
    const float* bv  = (const float*)d_in[6];
    const float* Wo  = (const float*)d_in[7];
    const float* bo  = (const float*)d_in[8];
    const float* rel = (const float*)d_in[9];
    const unsigned int* kpm = (const unsigned int*)d_in[10];
    float* out = (float*)d_out;

    float *qp, *kp, *vp, *ap;
    cudaGetSymbolAddress((void**)&qp, g_q);
    cudaGetSymbolAddress((void**)&kp, g_k);
    cudaGetSymbolAddress((void**)&vp, g_v);
    cudaGetSymbolAddress((void**)&ap, g_att);

    dim3 qkv_grid(D_ / 64, M_ / 64, 3);   // (8, 256, 3)
    qkv_gemm<<<qkv_grid, 256>>>(x, Wq, bq, Wk, bk, Wv, bv, qp, kp, vp);

    dim3 at_grid(T_ / 64, B_ * H_);       // (8, 256)
    attn_kernel<<<at_grid, 256>>>(qp, kp, vp, rel, kpm, ap);

    dim3 gemm_grid(D_ / 64, M_ / 64);     // (8, 256)
    out_gemm<<<gemm_grid, 256>>>(ap, Wo, bo, out);
}

// round 7
// speedup vs baseline: 1.5051x; 1.2293x over previous
#include <cuda_runtime.h>

#define B_   32
#define T_   512
#define D_   512
#define H_   8
#define DK_  64
#define M_   (B_ * T_)   // 16384

// ---- scratch (no allocations allowed) ----
__device__ float g_q[M_ * D_];
__device__ float g_k[M_ * D_];
__device__ float g_v[M_ * D_];
__device__ float g_att[M_ * D_];

// ============================================================================
// C[M,512] = A[M,512] @ W[512,512]^T + bias   (NT, K-contiguous both sides)
// 128x128 block tile, BK=16, 256 threads, 8x8 per-thread tile (split-half
// fragments at +0/+64 -> aligned float4, conflict-free smem reads).
// Staging transposed [kk][row] with stride 132 (2-way store conflicts only).
// Register prefetch of next global k-slab. 1 B-smem/FMA -> FMA-bound.
// ============================================================================
__device__ __forceinline__ void sgemm_body128(
    const float* __restrict__ A, const float* __restrict__ W,
    const float* __restrict__ bias, float* __restrict__ C)
{
    __shared__ __align__(16) float As[16][132];
    __shared__ __align__(16) float Bs[16][132];

    const int m0  = blockIdx.y * 128;
    const int n0  = blockIdx.x * 128;
    const int tid = threadIdx.x;
    const int tx  = tid & 15;          // col groups tx*4, tx*4+64
    const int ty  = tid >> 4;          // row groups ty*4, ty*4+64
    const int lr  = tid >> 2;          // load rows lr, lr+64
    const int lc  = (tid & 3) << 2;    // k-chunk {0,4,8,12}

    const float* Ap = A + (size_t)(m0 + lr) * 512 + lc;
    const float* Wp = W + (size_t)(n0 + lr) * 512 + lc;
    const size_t half = (size_t)64 * 512;

    float acc[8][8] = {};

    float4 a0 = *(const float4*)(Ap);
    float4 a1 = *(const float4*)(Ap + half);
    float4 w0 = *(const float4*)(Wp);
    float4 w1 = *(const float4*)(Wp + half);

    for (int k0 = 0; k0 < 512; k0 += 16) {
        As[lc+0][lr]    = a0.x; As[lc+1][lr]    = a0.y; As[lc+2][lr]    = a0.z; As[lc+3][lr]    = a0.w;
        As[lc+0][lr+64] = a1.x; As[lc+1][lr+64] = a1.y; As[lc+2][lr+64] = a1.z; As[lc+3][lr+64] = a1.w;
        Bs[lc+0][lr]    = w0.x; Bs[lc+1][lr]    = w0.y; Bs[lc+2][lr]    = w0.z; Bs[lc+3][lr]    = w0.w;
        Bs[lc+0][lr+64] = w1.x; Bs[lc+1][lr+64] = w1.y; Bs[lc+2][lr+64] = w1.z; Bs[lc+3][lr+64] = w1.w;
        __syncthreads();

        if (k0 + 16 < 512) {
            a0 = *(const float4*)(Ap + k0 + 16);
            a1 = *(const float4*)(Ap + half + k0 + 16);
            w0 = *(const float4*)(Wp + k0 + 16);
            w1 = *(const float4*)(Wp + half + k0 + 16);
        }

        #pragma unroll
        for (int kk = 0; kk < 16; kk++) {
            float4 x0 = *(const float4*)&As[kk][ty * 4];
            float4 x1 = *(const float4*)&As[kk][ty * 4 + 64];
            float4 y0 = *(const float4*)&Bs[kk][tx * 4];
            float4 y1 = *(const float4*)&Bs[kk][tx * 4 + 64];
            float a[8] = {x0.x, x0.y, x0.z, x0.w, x1.x, x1.y, x1.z, x1.w};
            float b[8] = {y0.x, y0.y, y0.z, y0.w, y1.x, y1.y, y1.z, y1.w};
            #pragma unroll
            for (int i = 0; i < 8; i++)
                #pragma unroll
                for (int j = 0; j < 8; j++)
                    acc[i][j] = fmaf(a[i], b[j], acc[i][j]);
        }
        __syncthreads();
    }

    float4 bb0 = *(const float4*)(bias + n0 + tx * 4);
    float4 bb1 = *(const float4*)(bias + n0 + tx * 4 + 64);
    float bj[8] = {bb0.x, bb0.y, bb0.z, bb0.w, bb1.x, bb1.y, bb1.z, bb1.w};

    #pragma unroll
    for (int ih = 0; ih < 2; ih++)
        #pragma unroll
        for (int i = 0; i < 4; i++) {
            float* cp = C + (size_t)(m0 + ih * 64 + ty * 4 + i) * 512 + n0 + tx * 4;
            int r = ih * 4 + i;
            float4 o0, o1;
            o0.x = acc[r][0] + bj[0]; o0.y = acc[r][1] + bj[1];
            o0.z = acc[r][2] + bj[2]; o0.w = acc[r][3] + bj[3];
            o1.x = acc[r][4] + bj[4]; o1.y = acc[r][5] + bj[5];
            o1.z = acc[r][6] + bj[6]; o1.w = acc[r][7] + bj[7];
            *(float4*)(cp)      = o0;
            *(float4*)(cp + 64) = o1;
        }
}

// Fused Q/K/V projection: blockIdx.z selects the weight/bias/output set.
__global__ __launch_bounds__(256, 2) void qkv_gemm(
    const float* __restrict__ A,
    const float* __restrict__ Wq, const float* __restrict__ bq,
    const float* __restrict__ Wk, const float* __restrict__ bk,
    const float* __restrict__ Wv, const float* __restrict__ bv,
    float* __restrict__ Cq, float* __restrict__ Ck, float* __restrict__ Cv)
{
    const int z = blockIdx.z;
    const float* W    = (z == 0) ? Wq : (z == 1) ? Wk : Wv;
    const float* bias = (z == 0) ? bq : (z == 1) ? bk : bv;
    float*       C    = (z == 0) ? Cq : (z == 1) ? Ck : Cv;
    sgemm_body128(A, W, bias, C);
}

__global__ __launch_bounds__(256, 2) void out_gemm(
    const float* __restrict__ A, const float* __restrict__ W,
    const float* __restrict__ bias, float* __restrict__ C)
{
    sgemm_body128(A, W, bias, C);
}

// ============================================================================
// Flash attention, 64 queries/block, 8 key tiles of 64, online softmax.
// XOR-swizzled transposed tiles (conflict-free). Unchanged from prior round.
// ============================================================================
#define SWZ(d, t) (((d) << 6) + (((((t) >> 2) ^ ((d) >> 2)) & 15) << 2) + ((t) & 3))
#define SWZ4(d, tg) (((d) << 6) + ((((tg) ^ ((d) >> 2)) & 15) << 2))

__global__ __launch_bounds__(256) void attn_kernel(
    const float* __restrict__ Q, const float* __restrict__ Kg,
    const float* __restrict__ Vg,
    const float* __restrict__ rel,           // [1023, 8]
    const unsigned int* __restrict__ kpm,    // [B, T], nonzero word => masked
    float* __restrict__ out)                 // [B, T, H, DK]
{
    __shared__ __align__(16) float Qt[64 * 64];   // swizzled [d][token]
    __shared__ __align__(16) float KP[64 * 64];   // swizzled Kt, then Pt
    __shared__ __align__(16) float Vs[64 * 64];   // row-major [tok][d]

    const int bh = blockIdx.y;
    const int b  = bh >> 3;
    const int h  = bh & 7;
    const int q0 = blockIdx.x * 64;
    const int tid = threadIdx.x;
    const int ty = tid >> 4;
    const int tx = tid & 15;
    const int ldr = tid >> 4;
    const int ldc = (tid & 15) * 4;

    {
        const float* qg = Q + ((size_t)(b * T_ + q0)) * D_ + h * DK_;
        #pragma unroll
        for (int rep = 0; rep < 4; rep++) {
            int r = ldr + rep * 16;
            float4 v = *(const float4*)(qg + (size_t)r * D_ + ldc);
            Qt[SWZ(ldc + 0, r)] = v.x;
            Qt[SWZ(ldc + 1, r)] = v.y;
            Qt[SWZ(ldc + 2, r)] = v.z;
            Qt[SWZ(ldc + 3, r)] = v.w;
        }
    }

    float m[4], l[4], o[4][4];
    #pragma unroll
    for (int i = 0; i < 4; i++) {
        m[i] = -1e30f; l[i] = 0.f;
        #pragma unroll
        for (int j = 0; j < 4; j++) o[i][j] = 0.f;
    }

    for (int kt = 0; kt < 8; kt++) {
        const int k0 = kt * 64;
        __syncthreads();

        const float* kg = Kg + ((size_t)(b * T_ + k0)) * D_ + h * DK_;
        const float* vg = Vg + ((size_t)(b * T_ + k0)) * D_ + h * DK_;
        #pragma unroll
        for (int rep = 0; rep < 4; rep++) {
            int r = ldr + rep * 16;
            float4 kv = *(const float4*)(kg + (size_t)r * D_ + ldc);
            KP[SWZ(ldc + 0, r)] = kv.x;
            KP[SWZ(ldc + 1, r)] = kv.y;
            KP[SWZ(ldc + 2, r)] = kv.z;
            KP[SWZ(ldc + 3, r)] = kv.w;
            float4 vv = *(const float4*)(vg + (size_t)r * D_ + ldc);
            *(float4*)&Vs[r * 64 + ldc] = vv;
        }
        __syncthreads();

        float s[4][4] = {};
        #pragma unroll 16
        for (int d = 0; d < 64; d++) {
            float4 a4 = *(const float4*)&Qt[SWZ4(d, ty)];
            float4 b4 = *(const float4*)&KP[SWZ4(d, tx)];
            float a[4] = {a4.x, a4.y, a4.z, a4.w};
            float bb[4] = {b4.x, b4.y, b4.z, b4.w};
            #pragma unroll
            for (int i = 0; i < 4; i++)
                #pragma unroll
                for (int j = 0; j < 4; j++)
                    s[i][j] = fmaf(a[i], bb[j], s[i][j]);
        }
        __syncthreads();

        const int base = (k0 + tx * 4 - q0 - ty * 4 + 511) * 8 + h;
        float r7[7];
        #pragma unroll
        for (int u = 0; u < 7; u++) r7[u] = __ldg(&rel[base + (u - 3) * 8]);
        uint4 mw = *(const uint4*)&kpm[b * T_ + k0 + tx * 4];
        float madd[4];
        madd[0] = mw.x ? -2e30f : 0.f;
        madd[1] = mw.y ? -2e30f : 0.f;
        madd[2] = mw.z ? -2e30f : 0.f;
        madd[3] = mw.w ? -2e30f : 0.f;

        #pragma unroll
        for (int i = 0; i < 4; i++)
            #pragma unroll
            for (int j = 0; j < 4; j++)
                s[i][j] = fmaf(s[i][j], 0.125f, r7[j - i + 3] + madd[j]);

        #pragma unroll
        for (int i = 0; i < 4; i++) {
            float rm = fmaxf(fmaxf(s[i][0], s[i][1]), fmaxf(s[i][2], s[i][3]));
            #pragma unroll
            for (int off = 8; off >= 1; off >>= 1)
                rm = fmaxf(rm, __shfl_xor_sync(0xffffffffu, rm, off));
            float mn = fmaxf(m[i], rm);
            float alpha = __expf(m[i] - mn);
            m[i] = mn;
            float rs = 0.f;
            #pragma unroll
            for (int j = 0; j < 4; j++) {
                float p = __expf(s[i][j] - mn);
                s[i][j] = p;
                rs += p;
            }
            #pragma unroll
            for (int off = 8; off >= 1; off >>= 1)
                rs += __shfl_xor_sync(0xffffffffu, rs, off);
            l[i] = l[i] * alpha + rs;
            #pragma unroll
            for (int j = 0; j < 4; j++) o[i][j] *= alpha;
        }

        #pragma unroll
        for (int j = 0; j < 4; j++) {
            float4 pv;
            pv.x = s[0][j]; pv.y = s[1][j]; pv.z = s[2][j]; pv.w = s[3][j];
            *(float4*)&KP[SWZ4(tx * 4 + j, ty)] = pv;
        }
        __syncthreads();

        #pragma unroll 16
        for (int k = 0; k < 64; k++) {
            float4 a4 = *(const float4*)&KP[SWZ4(k, ty)];
            float4 b4 = *(const float4*)&Vs[k * 64 + tx * 4];
            float a[4] = {a4.x, a4.y, a4.z, a4.w};
            float bb[4] = {b4.x, b4.y, b4.z, b4.w};
            #pragma unroll
            for (int i = 0; i < 4; i++)
                #pragma unroll
                for (int j = 0; j < 4; j++)
                    o[i][j] = fmaf(a[i], bb[j], o[i][j]);
        }
    }

    #pragma unroll
    for (int i = 0; i < 4; i++) {
        float inv = 1.f / l[i];
        float4 ov;
        ov.x = o[i][0] * inv; ov.y = o[i][1] * inv;
        ov.z = o[i][2] * inv; ov.w = o[i][3] * inv;
        *(float4*)(out + ((size_t)(b * T_ + q0 + ty * 4 + i)) * D_ + h * DK_ + tx * 4) = ov;
    }
}

// ============================================================================
extern "C" void kernel_launch(void* const* d_in, const int* in_sizes, int n_in,
                              void* d_out, int out_size)
{
    const float* x   = (const float*)d_in[0];
    const float* Wq  = (const float*)d_in[1];
    const float* bq  = (const float*)d_in[2];
    const float* Wk  = (const float*)d_in[3];
    const float* bk  = (const float*)d_in[4];
    const float* Wv  = (const float*)d_in[5];
    const float* bv  = (const float*)d_in[6];
    const float* Wo  = (const float*)d_in[7];
    const float* bo  = (const float*)d_in[8];
    const float* rel = (const float*)d_in[9];
    const unsigned int* kpm = (const unsigned int*)d_in[10];
    float* out = (float*)d_out;

    float *qp, *kp, *vp, *ap;
    cudaGetSymbolAddress((void**)&qp, g_q);
    cudaGetSymbolAddress((void**)&kp, g_k);
    cudaGetSymbolAddress((void**)&vp, g_v);
    cudaGetSymbolAddress((void**)&ap, g_att);

    dim3 qkv_grid(D_ / 128, M_ / 128, 3);   // (4, 128, 3) = 1536 blocks
    qkv_gemm<<<qkv_grid, 256>>>(x, Wq, bq, Wk, bk, Wv, bv, qp, kp, vp);

    dim3 at_grid(T_ / 64, B_ * H_);         // (8, 256)
    attn_kernel<<<at_grid, 256>>>(qp, kp, vp, rel, kpm, ap);

    dim3 gemm_grid(D_ / 128, M_ / 128);     // (4, 128)
    out_gemm<<<gemm_grid, 256>>>(ap, Wo, bo, out);
}

// round 8
// speedup vs baseline: 1.9791x; 1.3149x over previous
#include <cuda_runtime.h>
#include <cstdint>

#define B_   32
#define T_   512
#define D_   512
#define H_   8
#define DK_  64
#define M_   (B_ * T_)   // 16384

// ---- scratch (no allocations allowed) ----
__device__ float g_q[M_ * D_];
__device__ float g_k[M_ * D_];
__device__ float g_v[M_ * D_];
__device__ float g_att[M_ * D_];

// ============================================================================
// tf32 helpers
// ============================================================================
__device__ __forceinline__ uint32_t f32_tf32(float x) {
    uint32_t u;
    asm("cvt.rna.tf32.f32 %0, %1;" : "=r"(u) : "f"(x));
    return u;
}

__device__ __forceinline__ void mma_tf32(float c[4],
    uint32_t a0, uint32_t a1, uint32_t a2, uint32_t a3,
    uint32_t b0, uint32_t b1)
{
    asm volatile(
        "mma.sync.aligned.m16n8k8.row.col.f32.tf32.tf32.f32 "
        "{%0,%1,%2,%3}, {%4,%5,%6,%7}, {%8,%9}, {%0,%1,%2,%3};\n"
        : "+f"(c[0]), "+f"(c[1]), "+f"(c[2]), "+f"(c[3])
        : "r"(a0), "r"(a1), "r"(a2), "r"(a3), "r"(b0), "r"(b1));
}

// ============================================================================
// C[M,512] = A[M,512] @ W[512,512]^T + bias   via tf32 tensor cores.
// 128x128 block tile, BK=16, 256 threads = 8 warps in a 4(m) x 2(n) grid,
// warp tile 32(m) x 64(n) = 2 m-frags x 8 n-frags of m16n8k8.
// Smem staged transposed [k][m] / [k][n] (stride 132), values pre-rounded to
// tf32 (cvt.rna). Register prefetch of the next global k-slab.
// ============================================================================
__device__ __forceinline__ void gemm_tf32_body(
    const float* __restrict__ A, const float* __restrict__ W,
    const float* __restrict__ bias, float* __restrict__ C)
{
    __shared__ __align__(16) uint32_t As[16][132];   // [k][m] tf32 bits
    __shared__ __align__(16) uint32_t Bs[16][132];   // [k][n] tf32 bits

    const int m0  = blockIdx.y * 128;
    const int n0  = blockIdx.x * 128;
    const int tid = threadIdx.x;
    const int lane = tid & 31;
    const int warp = tid >> 5;
    const int wm0 = (warp >> 1) * 32;   // warp m-offset (0,32,64,96)
    const int wn0 = (warp & 1) * 64;    // warp n-offset (0,64)
    const int r   = lane >> 2;          // 0..7
    const int cq  = lane & 3;           // 0..3

    const int lr  = tid >> 2;           // staging rows lr, lr+64
    const int lc  = (tid & 3) << 2;     // staging k-chunk

    const float* Ap = A + (size_t)(m0 + lr) * 512 + lc;
    const float* Wp = W + (size_t)(n0 + lr) * 512 + lc;
    const size_t half = (size_t)64 * 512;

    float acc[2][8][4];
    #pragma unroll
    for (int mt = 0; mt < 2; mt++)
        #pragma unroll
        for (int nt = 0; nt < 8; nt++)
            #pragma unroll
            for (int i = 0; i < 4; i++) acc[mt][nt][i] = 0.f;

    float4 a0 = *(const float4*)(Ap);
    float4 a1 = *(const float4*)(Ap + half);
    float4 w0 = *(const float4*)(Wp);
    float4 w1 = *(const float4*)(Wp + half);

    for (int k0 = 0; k0 < 512; k0 += 16) {
        As[lc+0][lr]    = f32_tf32(a0.x); As[lc+1][lr]    = f32_tf32(a0.y);
        As[lc+2][lr]    = f32_tf32(a0.z); As[lc+3][lr]    = f32_tf32(a0.w);
        As[lc+0][lr+64] = f32_tf32(a1.x); As[lc+1][lr+64] = f32_tf32(a1.y);
        As[lc+2][lr+64] = f32_tf32(a1.z); As[lc+3][lr+64] = f32_tf32(a1.w);
        Bs[lc+0][lr]    = f32_tf32(w0.x); Bs[lc+1][lr]    = f32_tf32(w0.y);
        Bs[lc+2][lr]    = f32_tf32(w0.z); Bs[lc+3][lr]    = f32_tf32(w0.w);
        Bs[lc+0][lr+64] = f32_tf32(w1.x); Bs[lc+1][lr+64] = f32_tf32(w1.y);
        Bs[lc+2][lr+64] = f32_tf32(w1.z); Bs[lc+3][lr+64] = f32_tf32(w1.w);
        __syncthreads();

        if (k0 + 16 < 512) {
            a0 = *(const float4*)(Ap + k0 + 16);
            a1 = *(const float4*)(Ap + half + k0 + 16);
            w0 = *(const float4*)(Wp + k0 + 16);
            w1 = *(const float4*)(Wp + half + k0 + 16);
        }

        #pragma unroll
        for (int ks = 0; ks < 2; ks++) {
            const int kb = ks * 8;
            // A fragments: a0: (row=r, k=cq) a1: (r+8, cq) a2: (r, cq+4) a3: (r+8, cq+4)
            uint32_t af[2][4];
            #pragma unroll
            for (int mt = 0; mt < 2; mt++) {
                const int mb = wm0 + mt * 16;
                af[mt][0] = As[kb + cq]    [mb + r];
                af[mt][1] = As[kb + cq]    [mb + r + 8];
                af[mt][2] = As[kb + cq + 4][mb + r];
                af[mt][3] = As[kb + cq + 4][mb + r + 8];
            }
            // B fragments: b0: (k=cq, n=r)  b1: (k=cq+4, n=r)
            uint32_t bf[8][2];
            #pragma unroll
            for (int nt = 0; nt < 8; nt++) {
                const int nb = wn0 + nt * 8;
                bf[nt][0] = Bs[kb + cq]    [nb + r];
                bf[nt][1] = Bs[kb + cq + 4][nb + r];
            }
            #pragma unroll
            for (int mt = 0; mt < 2; mt++)
                #pragma unroll
                for (int nt = 0; nt < 8; nt++)
                    mma_tf32(acc[mt][nt], af[mt][0], af[mt][1], af[mt][2], af[mt][3],
                             bf[nt][0], bf[nt][1]);
        }
        __syncthreads();
    }

    // Epilogue: c0:(r, 2cq) c1:(r, 2cq+1) c2:(r+8, 2cq) c3:(r+8, 2cq+1)
    #pragma unroll
    for (int nt = 0; nt < 8; nt++) {
        const int n = n0 + wn0 + nt * 8 + 2 * cq;
        const float2 bv = *(const float2*)(bias + n);
        #pragma unroll
        for (int mt = 0; mt < 2; mt++) {
            const int row = m0 + wm0 + mt * 16 + r;
            float2 o0, o1;
            o0.x = acc[mt][nt][0] + bv.x; o0.y = acc[mt][nt][1] + bv.y;
            o1.x = acc[mt][nt][2] + bv.x; o1.y = acc[mt][nt][3] + bv.y;
            *(float2*)(C + (size_t)row * 512 + n)       = o0;
            *(float2*)(C + (size_t)(row + 8) * 512 + n) = o1;
        }
    }
}

// Fused Q/K/V projection: blockIdx.z selects the weight/bias/output set.
__global__ __launch_bounds__(256, 2) void qkv_gemm(
    const float* __restrict__ A,
    const float* __restrict__ Wq, const float* __restrict__ bq,
    const float* __restrict__ Wk, const float* __restrict__ bk,
    const float* __restrict__ Wv, const float* __restrict__ bv,
    float* __restrict__ Cq, float* __restrict__ Ck, float* __restrict__ Cv)
{
    const int z = blockIdx.z;
    const float* W    = (z == 0) ? Wq : (z == 1) ? Wk : Wv;
    const float* bias = (z == 0) ? bq : (z == 1) ? bk : bv;
    float*       C    = (z == 0) ? Cq : (z == 1) ? Ck : Cv;
    gemm_tf32_body(A, W, bias, C);
}

__global__ __launch_bounds__(256, 2) void out_gemm(
    const float* __restrict__ A, const float* __restrict__ W,
    const float* __restrict__ bias, float* __restrict__ C)
{
    gemm_tf32_body(A, W, bias, C);
}

// ============================================================================
// Flash attention, 64 queries/block, 8 key tiles of 64, online softmax.
// XOR-swizzled transposed tiles (conflict-free). Unchanged this round.
// ============================================================================
#define SWZ(d, t) (((d) << 6) + (((((t) >> 2) ^ ((d) >> 2)) & 15) << 2) + ((t) & 3))
#define SWZ4(d, tg) (((d) << 6) + ((((tg) ^ ((d) >> 2)) & 15) << 2))

__global__ __launch_bounds__(256) void attn_kernel(
    const float* __restrict__ Q, const float* __restrict__ Kg,
    const float* __restrict__ Vg,
    const float* __restrict__ rel,           // [1023, 8]
    const unsigned int* __restrict__ kpm,    // [B, T], nonzero word => masked
    float* __restrict__ out)                 // [B, T, H, DK]
{
    __shared__ __align__(16) float Qt[64 * 64];   // swizzled [d][token]
    __shared__ __align__(16) float KP[64 * 64];   // swizzled Kt, then Pt
    __shared__ __align__(16) float Vs[64 * 64];   // row-major [tok][d]

    const int bh = blockIdx.y;
    const int b  = bh >> 3;
    const int h  = bh & 7;
    const int q0 = blockIdx.x * 64;
    const int tid = threadIdx.x;
    const int ty = tid >> 4;
    const int tx = tid & 15;
    const int ldr = tid >> 4;
    const int ldc = (tid & 15) * 4;

    {
        const float* qg = Q + ((size_t)(b * T_ + q0)) * D_ + h * DK_;
        #pragma unroll
        for (int rep = 0; rep < 4; rep++) {
            int r = ldr + rep * 16;
            float4 v = *(const float4*)(qg + (size_t)r * D_ + ldc);
            Qt[SWZ(ldc + 0, r)] = v.x;
            Qt[SWZ(ldc + 1, r)] = v.y;
            Qt[SWZ(ldc + 2, r)] = v.z;
            Qt[SWZ(ldc + 3, r)] = v.w;
        }
    }

    float m[4], l[4], o[4][4];
    #pragma unroll
    for (int i = 0; i < 4; i++) {
        m[i] = -1e30f; l[i] = 0.f;
        #pragma unroll
        for (int j = 0; j < 4; j++) o[i][j] = 0.f;
    }

    for (int kt = 0; kt < 8; kt++) {
        const int k0 = kt * 64;
        __syncthreads();

        const float* kg = Kg + ((size_t)(b * T_ + k0)) * D_ + h * DK_;
        const float* vg = Vg + ((size_t)(b * T_ + k0)) * D_ + h * DK_;
        #pragma unroll
        for (int rep = 0; rep < 4; rep++) {
            int r = ldr + rep * 16;
            float4 kv = *(const float4*)(kg + (size_t)r * D_ + ldc);
            KP[SWZ(ldc + 0, r)] = kv.x;
            KP[SWZ(ldc + 1, r)] = kv.y;
            KP[SWZ(ldc + 2, r)] = kv.z;
            KP[SWZ(ldc + 3, r)] = kv.w;
            float4 vv = *(const float4*)(vg + (size_t)r * D_ + ldc);
            *(float4*)&Vs[r * 64 + ldc] = vv;
        }
        __syncthreads();

        float s[4][4] = {};
        #pragma unroll 16
        for (int d = 0; d < 64; d++) {
            float4 a4 = *(const float4*)&Qt[SWZ4(d, ty)];
            float4 b4 = *(const float4*)&KP[SWZ4(d, tx)];
            float a[4] = {a4.x, a4.y, a4.z, a4.w};
            float bb[4] = {b4.x, b4.y, b4.z, b4.w};
            #pragma unroll
            for (int i = 0; i < 4; i++)
                #pragma unroll
                for (int j = 0; j < 4; j++)
                    s[i][j] = fmaf(a[i], bb[j], s[i][j]);
        }
        __syncthreads();

        const int base = (k0 + tx * 4 - q0 - ty * 4 + 511) * 8 + h;
        float r7[7];
        #pragma unroll
        for (int u = 0; u < 7; u++) r7[u] = __ldg(&rel[base + (u - 3) * 8]);
        uint4 mw = *(const uint4*)&kpm[b * T_ + k0 + tx * 4];
        float madd[4];
        madd[0] = mw.x ? -2e30f : 0.f;
        madd[1] = mw.y ? -2e30f : 0.f;
        madd[2] = mw.z ? -2e30f : 0.f;
        madd[3] = mw.w ? -2e30f : 0.f;

        #pragma unroll
        for (int i = 0; i < 4; i++)
            #pragma unroll
            for (int j = 0; j < 4; j++)
                s[i][j] = fmaf(s[i][j], 0.125f, r7[j - i + 3] + madd[j]);

        #pragma unroll
        for (int i = 0; i < 4; i++) {
            float rm = fmaxf(fmaxf(s[i][0], s[i][1]), fmaxf(s[i][2], s[i][3]));
            #pragma unroll
            for (int off = 8; off >= 1; off >>= 1)
                rm = fmaxf(rm, __shfl_xor_sync(0xffffffffu, rm, off));
            float mn = fmaxf(m[i], rm);
            float alpha = __expf(m[i] - mn);
            m[i] = mn;
            float rs = 0.f;
            #pragma unroll
            for (int j = 0; j < 4; j++) {
                float p = __expf(s[i][j] - mn);
                s[i][j] = p;
                rs += p;
            }
            #pragma unroll
            for (int off = 8; off >= 1; off >>= 1)
                rs += __shfl_xor_sync(0xffffffffu, rs, off);
            l[i] = l[i] * alpha + rs;
            #pragma unroll
            for (int j = 0; j < 4; j++) o[i][j] *= alpha;
        }

        #pragma unroll
        for (int j = 0; j < 4; j++) {
            float4 pv;
            pv.x = s[0][j]; pv.y = s[1][j]; pv.z = s[2][j]; pv.w = s[3][j];
            *(float4*)&KP[SWZ4(tx * 4 + j, ty)] = pv;
        }
        __syncthreads();

        #pragma unroll 16
        for (int k = 0; k < 64; k++) {
            float4 a4 = *(const float4*)&KP[SWZ4(k, ty)];
            float4 b4 = *(const float4*)&Vs[k * 64 + tx * 4];
            float a[4] = {a4.x, a4.y, a4.z, a4.w};
            float bb[4] = {b4.x, b4.y, b4.z, b4.w};
            #pragma unroll
            for (int i = 0; i < 4; i++)
                #pragma unroll
                for (int j = 0; j < 4; j++)
                    o[i][j] = fmaf(a[i], bb[j], o[i][j]);
        }
    }

    #pragma unroll
    for (int i = 0; i < 4; i++) {
        float inv = 1.f / l[i];
        float4 ov;
        ov.x = o[i][0] * inv; ov.y = o[i][1] * inv;
        ov.z = o[i][2] * inv; ov.w = o[i][3] * inv;
        *(float4*)(out + ((size_t)(b * T_ + q0 + ty * 4 + i)) * D_ + h * DK_ + tx * 4) = ov;
    }
}

// ============================================================================
extern "C" void kernel_launch(void* const* d_in, const int* in_sizes, int n_in,
                              void* d_out, int out_size)
{
    const float* x   = (const float*)d_in[0];
    const float* Wq  = (const float*)d_in[1];
    const float* bq  = (const float*)d_in[2];
    const float* Wk  = (const float*)d_in[3];
    const float* bk  = (const float*)d_in[4];
    const float* Wv  = (const float*)d_in[5];
    const float* bv  = (const float*)d_in[6];
    const float* Wo  = (const float*)d_in[7];
    const float* bo  = (const float*)d_in[8];
    const float* rel = (const float*)d_in[9];
    const unsigned int* kpm = (const unsigned int*)d_in[10];
    float* out = (float*)d_out;

    float *qp, *kp, *vp, *ap;
    cudaGetSymbolAddress((void**)&qp, g_q);
    cudaGetSymbolAddress((void**)&kp, g_k);
    cudaGetSymbolAddress((void**)&vp, g_v);
    cudaGetSymbolAddress((void**)&ap, g_att);

    dim3 qkv_grid(D_ / 128, M_ / 128, 3);   // (4, 128, 3)
    qkv_gemm<<<qkv_grid, 256>>>(x, Wq, bq, Wk, bk, Wv, bv, qp, kp, vp);

    dim3 at_grid(T_ / 64, B_ * H_);         // (8, 256)
    attn_kernel<<<at_grid, 256>>>(qp, kp, vp, rel, kpm, ap);

    dim3 gemm_grid(D_ / 128, M_ / 128);     // (4, 128)
    out_gemm<<<gemm_grid, 256>>>(ap, Wo, bo, out);
}

// round 9
// speedup vs baseline: 2.7075x; 1.3681x over previous
#include <cuda_runtime.h>
#include <cstdint>

#define B_   32
#define T_   512
#define D_   512
#define H_   8
#define DK_  64
#define M_   (B_ * T_)   // 16384

// ---- scratch (no allocations allowed) ----
__device__ float g_q[M_ * D_];
__device__ float g_k[M_ * D_];
__device__ float g_v[M_ * D_];
__device__ float g_att[M_ * D_];

// ============================================================================
// tf32 helpers
// ============================================================================
__device__ __forceinline__ uint32_t f32_tf32(float x) {
    uint32_t u;
    asm("cvt.rna.tf32.f32 %0, %1;" : "=r"(u) : "f"(x));
    return u;
}
__device__ __forceinline__ float tf32f(float x) {   // round to tf32, keep as float
    uint32_t u = f32_tf32(x);
    return __uint_as_float(u);
}

__device__ __forceinline__ void mma_tf32(float c[4],
    uint32_t a0, uint32_t a1, uint32_t a2, uint32_t a3,
    uint32_t b0, uint32_t b1)
{
    asm volatile(
        "mma.sync.aligned.m16n8k8.row.col.f32.tf32.tf32.f32 "
        "{%0,%1,%2,%3}, {%4,%5,%6,%7}, {%8,%9}, {%0,%1,%2,%3};\n"
        : "+f"(c[0]), "+f"(c[1]), "+f"(c[2]), "+f"(c[3])
        : "r"(a0), "r"(a1), "r"(a2), "r"(a3), "r"(b0), "r"(b1));
}

// ============================================================================
// Projection GEMM via tf32 tensor cores (unchanged from passing round 8).
// ============================================================================
__device__ __forceinline__ void gemm_tf32_body(
    const float* __restrict__ A, const float* __restrict__ W,
    const float* __restrict__ bias, float* __restrict__ C)
{
    __shared__ __align__(16) uint32_t As[16][132];
    __shared__ __align__(16) uint32_t Bs[16][132];

    const int m0  = blockIdx.y * 128;
    const int n0  = blockIdx.x * 128;
    const int tid = threadIdx.x;
    const int lane = tid & 31;
    const int warp = tid >> 5;
    const int wm0 = (warp >> 1) * 32;
    const int wn0 = (warp & 1) * 64;
    const int r   = lane >> 2;
    const int cq  = lane & 3;

    const int lr  = tid >> 2;
    const int lc  = (tid & 3) << 2;

    const float* Ap = A + (size_t)(m0 + lr) * 512 + lc;
    const float* Wp = W + (size_t)(n0 + lr) * 512 + lc;
    const size_t half = (size_t)64 * 512;

    float acc[2][8][4];
    #pragma unroll
    for (int mt = 0; mt < 2; mt++)
        #pragma unroll
        for (int nt = 0; nt < 8; nt++)
            #pragma unroll
            for (int i = 0; i < 4; i++) acc[mt][nt][i] = 0.f;

    float4 a0 = *(const float4*)(Ap);
    float4 a1 = *(const float4*)(Ap + half);
    float4 w0 = *(const float4*)(Wp);
    float4 w1 = *(const float4*)(Wp + half);

    for (int k0 = 0; k0 < 512; k0 += 16) {
        As[lc+0][lr]    = f32_tf32(a0.x); As[lc+1][lr]    = f32_tf32(a0.y);
        As[lc+2][lr]    = f32_tf32(a0.z); As[lc+3][lr]    = f32_tf32(a0.w);
        As[lc+0][lr+64] = f32_tf32(a1.x); As[lc+1][lr+64] = f32_tf32(a1.y);
        As[lc+2][lr+64] = f32_tf32(a1.z); As[lc+3][lr+64] = f32_tf32(a1.w);
        Bs[lc+0][lr]    = f32_tf32(w0.x); Bs[lc+1][lr]    = f32_tf32(w0.y);
        Bs[lc+2][lr]    = f32_tf32(w0.z); Bs[lc+3][lr]    = f32_tf32(w0.w);
        Bs[lc+0][lr+64] = f32_tf32(w1.x); Bs[lc+1][lr+64] = f32_tf32(w1.y);
        Bs[lc+2][lr+64] = f32_tf32(w1.z); Bs[lc+3][lr+64] = f32_tf32(w1.w);
        __syncthreads();

        if (k0 + 16 < 512) {
            a0 = *(const float4*)(Ap + k0 + 16);
            a1 = *(const float4*)(Ap + half + k0 + 16);
            w0 = *(const float4*)(Wp + k0 + 16);
            w1 = *(const float4*)(Wp + half + k0 + 16);
        }

        #pragma unroll
        for (int ks = 0; ks < 2; ks++) {
            const int kb = ks * 8;
            uint32_t af[2][4];
            #pragma unroll
            for (int mt = 0; mt < 2; mt++) {
                const int mb = wm0 + mt * 16;
                af[mt][0] = As[kb + cq]    [mb + r];
                af[mt][1] = As[kb + cq]    [mb + r + 8];
                af[mt][2] = As[kb + cq + 4][mb + r];
                af[mt][3] = As[kb + cq + 4][mb + r + 8];
            }
            uint32_t bf[8][2];
            #pragma unroll
            for (int nt = 0; nt < 8; nt++) {
                const int nb = wn0 + nt * 8;
                bf[nt][0] = Bs[kb + cq]    [nb + r];
                bf[nt][1] = Bs[kb + cq + 4][nb + r];
            }
            #pragma unroll
            for (int mt = 0; mt < 2; mt++)
                #pragma unroll
                for (int nt = 0; nt < 8; nt++)
                    mma_tf32(acc[mt][nt], af[mt][0], af[mt][1], af[mt][2], af[mt][3],
                             bf[nt][0], bf[nt][1]);
        }
        __syncthreads();
    }

    #pragma unroll
    for (int nt = 0; nt < 8; nt++) {
        const int n = n0 + wn0 + nt * 8 + 2 * cq;
        const float2 bv = *(const float2*)(bias + n);
        #pragma unroll
        for (int mt = 0; mt < 2; mt++) {
            const int row = m0 + wm0 + mt * 16 + r;
            float2 o0, o1;
            o0.x = acc[mt][nt][0] + bv.x; o0.y = acc[mt][nt][1] + bv.y;
            o1.x = acc[mt][nt][2] + bv.x; o1.y = acc[mt][nt][3] + bv.y;
            *(float2*)(C + (size_t)row * 512 + n)       = o0;
            *(float2*)(C + (size_t)(row + 8) * 512 + n) = o1;
        }
    }
}

__global__ __launch_bounds__(256, 2) void qkv_gemm(
    const float* __restrict__ A,
    const float* __restrict__ Wq, const float* __restrict__ bq,
    const float* __restrict__ Wk, const float* __restrict__ bk,
    const float* __restrict__ Wv, const float* __restrict__ bv,
    float* __restrict__ Cq, float* __restrict__ Ck, float* __restrict__ Cv)
{
    const int z = blockIdx.z;
    const float* W    = (z == 0) ? Wq : (z == 1) ? Wk : Wv;
    const float* bias = (z == 0) ? bq : (z == 1) ? bk : bv;
    float*       C    = (z == 0) ? Cq : (z == 1) ? Ck : Cv;
    gemm_tf32_body(A, W, bias, C);
}

__global__ __launch_bounds__(256, 2) void out_gemm(
    const float* __restrict__ A, const float* __restrict__ W,
    const float* __restrict__ bias, float* __restrict__ C)
{
    gemm_tf32_body(A, W, bias, C);
}

// ============================================================================
// Tensor-core flash attention.
// Block = 64 queries of one (b,h); 128 threads = 4 warps, warp w owns query
// rows [w*16, w*16+16) and the FULL 64-key width (8 n-frags of m16n8k8) so
// softmax row reductions stay within a lane quad.
//   Q fragments: registers (fixed across all 8 key tiles), tf32.
//   Ks: [key][d]  stride 68 (B-frag reads: banks 4r+cq, conflict-free),
//       aliased by P [query][key] stride 68 after S is consumed.
//   Vs: [key][d]  stride 72 (B-frag reads: banks 8cq+r, conflict-free);
//       also used once to stage Q at kernel start.
//   bias/mask staged per key-tile into small smem LUTs, added in f32.
// ============================================================================
#define KS_STR 68
#define VS_STR 72

__global__ __launch_bounds__(128) void attn_tc(
    const float* __restrict__ Q, const float* __restrict__ Kg,
    const float* __restrict__ Vg,
    const float* __restrict__ rel,           // [1023, 8]
    const unsigned int* __restrict__ kpm,    // [B, T], nonzero word => masked
    float* __restrict__ out)                 // [B, T, H, DK]
{
    __shared__ __align__(16) float Ks[64 * KS_STR];   // K tile, then P
    __shared__ __align__(16) float Vs[64 * VS_STR];   // V tile (Q staging at start)
    __shared__ float bias_s[128];
    __shared__ float mask_s[64];

    const int bh = blockIdx.y;
    const int b  = bh >> 3;
    const int h  = bh & 7;
    const int q0 = blockIdx.x * 64;
    const int tid  = threadIdx.x;
    const int lane = tid & 31;
    const int warp = tid >> 5;
    const int r  = lane >> 2;     // 0..7
    const int cq = lane & 3;      // 0..3
    const int wm = warp * 16;     // query stripe base (local)

    const int sr = tid >> 1;            // staging row 0..63
    const int sc = (tid & 1) * 32;      // staging col half

    // ---- stage Q into Vs, then lift fragments to registers ----
    {
        const float* qg = Q + ((size_t)(b * T_ + q0)) * D_ + h * DK_;
        #pragma unroll
        for (int c = 0; c < 8; c++) {
            float4 v = *(const float4*)(qg + (size_t)sr * D_ + sc + c * 4);
            *(float4*)&Vs[sr * VS_STR + sc + c * 4] = v;
        }
    }
    __syncthreads();
    uint32_t qf[8][4];
    #pragma unroll
    for (int ks = 0; ks < 8; ks++) {
        qf[ks][0] = f32_tf32(Vs[(wm + r)     * VS_STR + ks * 8 + cq]);
        qf[ks][1] = f32_tf32(Vs[(wm + r + 8) * VS_STR + ks * 8 + cq]);
        qf[ks][2] = f32_tf32(Vs[(wm + r)     * VS_STR + ks * 8 + cq + 4]);
        qf[ks][3] = f32_tf32(Vs[(wm + r + 8) * VS_STR + ks * 8 + cq + 4]);
    }

    float m0 = -1e30f, m1 = -1e30f, l0 = 0.f, l1 = 0.f;
    float oacc[8][4];
    #pragma unroll
    for (int nt = 0; nt < 8; nt++)
        #pragma unroll
        for (int i = 0; i < 4; i++) oacc[nt][i] = 0.f;

    for (int kt = 0; kt < 8; kt++) {
        const int k0 = kt * 64;
        __syncthreads();   // Ks/Vs (and Q staging on kt=0) free for reuse

        // ---- stage K (stride 68) and V (stride 72), pre-rounded to tf32 ----
        const float* kg = Kg + ((size_t)(b * T_ + k0)) * D_ + h * DK_;
        const float* vg = Vg + ((size_t)(b * T_ + k0)) * D_ + h * DK_;
        #pragma unroll
        for (int c = 0; c < 8; c++) {
            float4 kv = *(const float4*)(kg + (size_t)sr * D_ + sc + c * 4);
            float4 kt4;
            kt4.x = tf32f(kv.x); kt4.y = tf32f(kv.y);
            kt4.z = tf32f(kv.z); kt4.w = tf32f(kv.w);
            *(float4*)&Ks[sr * KS_STR + sc + c * 4] = kt4;
            float4 vv = *(const float4*)(vg + (size_t)sr * D_ + sc + c * 4);
            float4 vt4;
            vt4.x = tf32f(vv.x); vt4.y = tf32f(vv.y);
            vt4.z = tf32f(vv.z); vt4.w = tf32f(vv.w);
            *(float4*)&Vs[sr * VS_STR + sc + c * 4] = vt4;
        }
        // bias LUT: diff = k - q in [k0-q0-63, k0-q0+63] -> 127 entries
        if (tid < 127)
            bias_s[tid] = __ldg(&rel[(k0 - q0 - 63 + tid + 511) * 8 + h]);
        if (tid < 64)
            mask_s[tid] = __ldg(&kpm[b * T_ + k0 + tid]) ? -2e30f : 0.f;
        __syncthreads();

        // ---- S = Q K^T (tf32 mma) ----
        float sacc[8][4];
        #pragma unroll
        for (int nt = 0; nt < 8; nt++)
            #pragma unroll
            for (int i = 0; i < 4; i++) sacc[nt][i] = 0.f;

        #pragma unroll
        for (int ks = 0; ks < 8; ks++) {
            #pragma unroll
            for (int nt = 0; nt < 8; nt++) {
                uint32_t b0 = __float_as_uint(Ks[(nt * 8 + r) * KS_STR + ks * 8 + cq]);
                uint32_t b1 = __float_as_uint(Ks[(nt * 8 + r) * KS_STR + ks * 8 + cq + 4]);
                mma_tf32(sacc[nt], qf[ks][0], qf[ks][1], qf[ks][2], qf[ks][3], b0, b1);
            }
        }

        // ---- scale + bias + mask (f32) ----
        const int rr0 = wm + r, rr1 = wm + r + 8;
        #pragma unroll
        for (int nt = 0; nt < 8; nt++) {
            const int cc = nt * 8 + 2 * cq;
            const float mk0 = mask_s[cc], mk1 = mask_s[cc + 1];
            sacc[nt][0] = fmaf(sacc[nt][0], 0.125f, bias_s[cc     - rr0 + 63] + mk0);
            sacc[nt][1] = fmaf(sacc[nt][1], 0.125f, bias_s[cc + 1 - rr0 + 63] + mk1);
            sacc[nt][2] = fmaf(sacc[nt][2], 0.125f, bias_s[cc     - rr1 + 63] + mk0);
            sacc[nt][3] = fmaf(sacc[nt][3], 0.125f, bias_s[cc + 1 - rr1 + 63] + mk1);
        }

        // ---- online softmax (rows r and r+8; reduce over quad lanes) ----
        float rm0 = -1e30f, rm1 = -1e30f;
        #pragma unroll
        for (int nt = 0; nt < 8; nt++) {
            rm0 = fmaxf(rm0, fmaxf(sacc[nt][0], sacc[nt][1]));
            rm1 = fmaxf(rm1, fmaxf(sacc[nt][2], sacc[nt][3]));
        }
        rm0 = fmaxf(rm0, __shfl_xor_sync(0xffffffffu, rm0, 1));
        rm0 = fmaxf(rm0, __shfl_xor_sync(0xffffffffu, rm0, 2));
        rm1 = fmaxf(rm1, __shfl_xor_sync(0xffffffffu, rm1, 1));
        rm1 = fmaxf(rm1, __shfl_xor_sync(0xffffffffu, rm1, 2));

        const float mn0 = fmaxf(m0, rm0), mn1 = fmaxf(m1, rm1);
        const float al0 = __expf(m0 - mn0), al1 = __expf(m1 - mn1);
        m0 = mn0; m1 = mn1;

        float rs0 = 0.f, rs1 = 0.f;
        #pragma unroll
        for (int nt = 0; nt < 8; nt++) {
            sacc[nt][0] = __expf(sacc[nt][0] - mn0);
            sacc[nt][1] = __expf(sacc[nt][1] - mn0);
            sacc[nt][2] = __expf(sacc[nt][2] - mn1);
            sacc[nt][3] = __expf(sacc[nt][3] - mn1);
            rs0 += sacc[nt][0] + sacc[nt][1];
            rs1 += sacc[nt][2] + sacc[nt][3];
        }
        rs0 += __shfl_xor_sync(0xffffffffu, rs0, 1);
        rs0 += __shfl_xor_sync(0xffffffffu, rs0, 2);
        rs1 += __shfl_xor_sync(0xffffffffu, rs1, 1);
        rs1 += __shfl_xor_sync(0xffffffffu, rs1, 2);
        l0 = l0 * al0 + rs0;
        l1 = l1 * al1 + rs1;
        #pragma unroll
        for (int nt = 0; nt < 8; nt++) {
            oacc[nt][0] *= al0; oacc[nt][1] *= al0;
            oacc[nt][2] *= al1; oacc[nt][3] *= al1;
        }

        __syncthreads();   // all warps done reading Ks before P overwrite

        // ---- write P (tf32-rounded) into Ks as [query][key] stride 68 ----
        #pragma unroll
        for (int nt = 0; nt < 8; nt++) {
            const int cc = nt * 8 + 2 * cq;
            float2 p0, p1;
            p0.x = tf32f(sacc[nt][0]); p0.y = tf32f(sacc[nt][1]);
            p1.x = tf32f(sacc[nt][2]); p1.y = tf32f(sacc[nt][3]);
            *(float2*)&Ks[rr0 * KS_STR + cc] = p0;
            *(float2*)&Ks[rr1 * KS_STR + cc] = p1;
        }
        __syncthreads();

        // ---- O += P V (tf32 mma) ----
        #pragma unroll
        for (int ks = 0; ks < 8; ks++) {
            uint32_t a0 = __float_as_uint(Ks[rr0 * KS_STR + ks * 8 + cq]);
            uint32_t a1 = __float_as_uint(Ks[rr1 * KS_STR + ks * 8 + cq]);
            uint32_t a2 = __float_as_uint(Ks[rr0 * KS_STR + ks * 8 + cq + 4]);
            uint32_t a3 = __float_as_uint(Ks[rr1 * KS_STR + ks * 8 + cq + 4]);
            #pragma unroll
            for (int nt = 0; nt < 8; nt++) {
                uint32_t b0 = __float_as_uint(Vs[(ks * 8 + cq)     * VS_STR + nt * 8 + r]);
                uint32_t b1 = __float_as_uint(Vs[(ks * 8 + cq + 4) * VS_STR + nt * 8 + r]);
                mma_tf32(oacc[nt], a0, a1, a2, a3, b0, b1);
            }
        }
    }

    // ---- epilogue: normalize and store ----
    const float inv0 = 1.f / l0, inv1 = 1.f / l1;
    const int row0 = b * T_ + q0 + wm + r;
    #pragma unroll
    for (int nt = 0; nt < 8; nt++) {
        const int col = h * DK_ + nt * 8 + 2 * cq;
        float2 o0, o1;
        o0.x = oacc[nt][0] * inv0; o0.y = oacc[nt][1] * inv0;
        o1.x = oacc[nt][2] * inv1; o1.y = oacc[nt][3] * inv1;
        *(float2*)(out + (size_t)row0 * D_ + col)       = o0;
        *(float2*)(out + (size_t)(row0 + 8) * D_ + col) = o1;
    }
}

// ============================================================================
extern "C" void kernel_launch(void* const* d_in, const int* in_sizes, int n_in,
                              void* d_out, int out_size)
{
    const float* x   = (const float*)d_in[0];
    const float* Wq  = (const float*)d_in[1];
    const float* bq  = (const float*)d_in[2];
    const float* Wk  = (const float*)d_in[3];
    const float* bk  = (const float*)d_in[4];
    const float* Wv  = (const float*)d_in[5];
    const float* bv  = (const float*)d_in[6];
    const float* Wo  = (const float*)d_in[7];
    const float* bo  = (const float*)d_in[8];
    const float* rel = (const float*)d_in[9];
    const unsigned int* kpm = (const unsigned int*)d_in[10];
    float* out = (float*)d_out;

    float *qp, *kp, *vp, *ap;
    cudaGetSymbolAddress((void**)&qp, g_q);
    cudaGetSymbolAddress((void**)&kp, g_k);
    cudaGetSymbolAddress((void**)&vp, g_v);
    cudaGetSymbolAddress((void**)&ap, g_att);

    dim3 qkv_grid(D_ / 128, M_ / 128, 3);   // (4, 128, 3)
    qkv_gemm<<<qkv_grid, 256>>>(x, Wq, bq, Wk, bk, Wv, bv, qp, kp, vp);

    dim3 at_grid(T_ / 64, B_ * H_);         // (8, 256)
    attn_tc<<<at_grid, 128>>>(qp, kp, vp, rel, kpm, ap);

    dim3 gemm_grid(D_ / 128, M_ / 128);     // (4, 128)
    out_gemm<<<gemm_grid, 256>>>(ap, Wo, bo, out);
}

// round 10
// speedup vs baseline: 2.7173x; 1.0036x over previous
#include <cuda_runtime.h>
#include <cstdint>

#define B_   32
#define T_   512
#define D_   512
#define H_   8
#define DK_  64
#define M_   (B_ * T_)   // 16384

// ---- scratch (no allocations allowed) ----
__device__ float g_q[M_ * D_];
__device__ float g_k[M_ * D_];
__device__ float g_v[M_ * D_];
__device__ float g_att[M_ * D_];

// ============================================================================
// tf32 helpers
// ============================================================================
__device__ __forceinline__ uint32_t f32_tf32(float x) {
    uint32_t u;
    asm("cvt.rna.tf32.f32 %0, %1;" : "=r"(u) : "f"(x));
    return u;
}
__device__ __forceinline__ float tf32f(float x) {
    uint32_t u = f32_tf32(x);
    return __uint_as_float(u);
}

__device__ __forceinline__ void mma_tf32(float c[4],
    uint32_t a0, uint32_t a1, uint32_t a2, uint32_t a3,
    uint32_t b0, uint32_t b1)
{
    asm volatile(
        "mma.sync.aligned.m16n8k8.row.col.f32.tf32.tf32.f32 "
        "{%0,%1,%2,%3}, {%4,%5,%6,%7}, {%8,%9}, {%0,%1,%2,%3};\n"
        : "+f"(c[0]), "+f"(c[1]), "+f"(c[2]), "+f"(c[3])
        : "r"(a0), "r"(a1), "r"(a2), "r"(a3), "r"(b0), "r"(b1));
}

// ============================================================================
// Projection GEMM via tf32 tensor cores, 2-stage double-buffered smem.
// 128x128 block tile, BK=16, 256 threads = 8 warps (4m x 2n), warp tile
// 32x64 = 2 m-frags x 8 n-frags of m16n8k8. One __syncthreads per k-slab.
// ============================================================================
__device__ __forceinline__ void gemm_tf32_body(
    const float* __restrict__ A, const float* __restrict__ W,
    const float* __restrict__ bias, float* __restrict__ C)
{
    __shared__ __align__(16) uint32_t As[2][16][132];
    __shared__ __align__(16) uint32_t Bs[2][16][132];

    const int m0  = blockIdx.y * 128;
    const int n0  = blockIdx.x * 128;
    const int tid = threadIdx.x;
    const int lane = tid & 31;
    const int warp = tid >> 5;
    const int wm0 = (warp >> 1) * 32;
    const int wn0 = (warp & 1) * 64;
    const int r   = lane >> 2;
    const int cq  = lane & 3;

    const int lr  = tid >> 2;
    const int lc  = (tid & 3) << 2;

    const float* Ap = A + (size_t)(m0 + lr) * 512 + lc;
    const float* Wp = W + (size_t)(n0 + lr) * 512 + lc;
    const size_t half = (size_t)64 * 512;

    float acc[2][8][4];
    #pragma unroll
    for (int mt = 0; mt < 2; mt++)
        #pragma unroll
        for (int nt = 0; nt < 8; nt++)
            #pragma unroll
            for (int i = 0; i < 4; i++) acc[mt][nt][i] = 0.f;

    float4 a0, a1, w0, w1;

    // ---- prologue: load + stage slab 0 into buffer 0 ----
    a0 = *(const float4*)(Ap);
    a1 = *(const float4*)(Ap + half);
    w0 = *(const float4*)(Wp);
    w1 = *(const float4*)(Wp + half);
    {
        uint32_t (*Ab)[132] = As[0];
        uint32_t (*Bb)[132] = Bs[0];
        Ab[lc+0][lr]    = f32_tf32(a0.x); Ab[lc+1][lr]    = f32_tf32(a0.y);
        Ab[lc+2][lr]    = f32_tf32(a0.z); Ab[lc+3][lr]    = f32_tf32(a0.w);
        Ab[lc+0][lr+64] = f32_tf32(a1.x); Ab[lc+1][lr+64] = f32_tf32(a1.y);
        Ab[lc+2][lr+64] = f32_tf32(a1.z); Ab[lc+3][lr+64] = f32_tf32(a1.w);
        Bb[lc+0][lr]    = f32_tf32(w0.x); Bb[lc+1][lr]    = f32_tf32(w0.y);
        Bb[lc+2][lr]    = f32_tf32(w0.z); Bb[lc+3][lr]    = f32_tf32(w0.w);
        Bb[lc+0][lr+64] = f32_tf32(w1.x); Bb[lc+1][lr+64] = f32_tf32(w1.y);
        Bb[lc+2][lr+64] = f32_tf32(w1.z); Bb[lc+3][lr+64] = f32_tf32(w1.w);
    }
    __syncthreads();

    #pragma unroll 2
    for (int k0 = 0; k0 < 512; k0 += 16) {
        const int buf = (k0 >> 4) & 1;
        const bool has_next = (k0 + 16) < 512;

        // prefetch next slab (latency covered by the MMA block below)
        if (has_next) {
            a0 = *(const float4*)(Ap + k0 + 16);
            a1 = *(const float4*)(Ap + half + k0 + 16);
            w0 = *(const float4*)(Wp + k0 + 16);
            w1 = *(const float4*)(Wp + half + k0 + 16);
        }

        // ---- compute slab k0 from buffer buf ----
        {
            uint32_t (*Ab)[132] = As[buf];
            uint32_t (*Bb)[132] = Bs[buf];
            #pragma unroll
            for (int ks = 0; ks < 2; ks++) {
                const int kb = ks * 8;
                uint32_t af[2][4];
                #pragma unroll
                for (int mt = 0; mt < 2; mt++) {
                    const int mb = wm0 + mt * 16;
                    af[mt][0] = Ab[kb + cq]    [mb + r];
                    af[mt][1] = Ab[kb + cq]    [mb + r + 8];
                    af[mt][2] = Ab[kb + cq + 4][mb + r];
                    af[mt][3] = Ab[kb + cq + 4][mb + r + 8];
                }
                uint32_t bf[8][2];
                #pragma unroll
                for (int nt = 0; nt < 8; nt++) {
                    const int nb = wn0 + nt * 8;
                    bf[nt][0] = Bb[kb + cq]    [nb + r];
                    bf[nt][1] = Bb[kb + cq + 4][nb + r];
                }
                #pragma unroll
                for (int mt = 0; mt < 2; mt++)
                    #pragma unroll
                    for (int nt = 0; nt < 8; nt++)
                        mma_tf32(acc[mt][nt], af[mt][0], af[mt][1], af[mt][2], af[mt][3],
                                 bf[nt][0], bf[nt][1]);
            }
        }

        // ---- stage prefetched slab into the other buffer ----
        // (safe: every warp finished reading buf^1 before the previous barrier)
        if (has_next) {
            uint32_t (*Ab)[132] = As[buf ^ 1];
            uint32_t (*Bb)[132] = Bs[buf ^ 1];
            Ab[lc+0][lr]    = f32_tf32(a0.x); Ab[lc+1][lr]    = f32_tf32(a0.y);
            Ab[lc+2][lr]    = f32_tf32(a0.z); Ab[lc+3][lr]    = f32_tf32(a0.w);
            Ab[lc+0][lr+64] = f32_tf32(a1.x); Ab[lc+1][lr+64] = f32_tf32(a1.y);
            Ab[lc+2][lr+64] = f32_tf32(a1.z); Ab[lc+3][lr+64] = f32_tf32(a1.w);
            Bb[lc+0][lr]    = f32_tf32(w0.x); Bb[lc+1][lr]    = f32_tf32(w0.y);
            Bb[lc+2][lr]    = f32_tf32(w0.z); Bb[lc+3][lr]    = f32_tf32(w0.w);
            Bb[lc+0][lr+64] = f32_tf32(w1.x); Bb[lc+1][lr+64] = f32_tf32(w1.y);
            Bb[lc+2][lr+64] = f32_tf32(w1.z); Bb[lc+3][lr+64] = f32_tf32(w1.w);
        }
        __syncthreads();
    }

    #pragma unroll
    for (int nt = 0; nt < 8; nt++) {
        const int n = n0 + wn0 + nt * 8 + 2 * cq;
        const float2 bv = *(const float2*)(bias + n);
        #pragma unroll
        for (int mt = 0; mt < 2; mt++) {
            const int row = m0 + wm0 + mt * 16 + r;
            float2 o0, o1;
            o0.x = acc[mt][nt][0] + bv.x; o0.y = acc[mt][nt][1] + bv.y;
            o1.x = acc[mt][nt][2] + bv.x; o1.y = acc[mt][nt][3] + bv.y;
            *(float2*)(C + (size_t)row * 512 + n)       = o0;
            *(float2*)(C + (size_t)(row + 8) * 512 + n) = o1;
        }
    }
}

__global__ __launch_bounds__(256, 2) void qkv_gemm(
    const float* __restrict__ A,
    const float* __restrict__ Wq, const float* __restrict__ bq,
    const float* __restrict__ Wk, const float* __restrict__ bk,
    const float* __restrict__ Wv, const float* __restrict__ bv,
    float* __restrict__ Cq, float* __restrict__ Ck, float* __restrict__ Cv)
{
    const int z = blockIdx.z;
    const float* W    = (z == 0) ? Wq : (z == 1) ? Wk : Wv;
    const float* bias = (z == 0) ? bq : (z == 1) ? bk : bv;
    float*       C    = (z == 0) ? Cq : (z == 1) ? Ck : Cv;
    gemm_tf32_body(A, W, bias, C);
}

__global__ __launch_bounds__(256, 2) void out_gemm(
    const float* __restrict__ A, const float* __restrict__ W,
    const float* __restrict__ bias, float* __restrict__ C)
{
    gemm_tf32_body(A, W, bias, C);
}

// ============================================================================
// Tensor-core flash attention (unchanged from passing round 9).
// ============================================================================
#define KS_STR 68
#define VS_STR 72

__global__ __launch_bounds__(128) void attn_tc(
    const float* __restrict__ Q, const float* __restrict__ Kg,
    const float* __restrict__ Vg,
    const float* __restrict__ rel,           // [1023, 8]
    const unsigned int* __restrict__ kpm,    // [B, T], nonzero word => masked
    float* __restrict__ out)                 // [B, T, H, DK]
{
    __shared__ __align__(16) float Ks[64 * KS_STR];   // K tile, then P
    __shared__ __align__(16) float Vs[64 * VS_STR];   // V tile (Q staging at start)
    __shared__ float bias_s[128];
    __shared__ float mask_s[64];

    const int bh = blockIdx.y;
    const int b  = bh >> 3;
    const int h  = bh & 7;
    const int q0 = blockIdx.x * 64;
    const int tid  = threadIdx.x;
    const int lane = tid & 31;
    const int warp = tid >> 5;
    const int r  = lane >> 2;
    const int cq = lane & 3;
    const int wm = warp * 16;

    const int sr = tid >> 1;
    const int sc = (tid & 1) * 32;

    {
        const float* qg = Q + ((size_t)(b * T_ + q0)) * D_ + h * DK_;
        #pragma unroll
        for (int c = 0; c < 8; c++) {
            float4 v = *(const float4*)(qg + (size_t)sr * D_ + sc + c * 4);
            *(float4*)&Vs[sr * VS_STR + sc + c * 4] = v;
        }
    }
    __syncthreads();
    uint32_t qf[8][4];
    #pragma unroll
    for (int ks = 0; ks < 8; ks++) {
        qf[ks][0] = f32_tf32(Vs[(wm + r)     * VS_STR + ks * 8 + cq]);
        qf[ks][1] = f32_tf32(Vs[(wm + r + 8) * VS_STR + ks * 8 + cq]);
        qf[ks][2] = f32_tf32(Vs[(wm + r)     * VS_STR + ks * 8 + cq + 4]);
        qf[ks][3] = f32_tf32(Vs[(wm + r + 8) * VS_STR + ks * 8 + cq + 4]);
    }

    float m0 = -1e30f, m1 = -1e30f, l0 = 0.f, l1 = 0.f;
    float oacc[8][4];
    #pragma unroll
    for (int nt = 0; nt < 8; nt++)
        #pragma unroll
        for (int i = 0; i < 4; i++) oacc[nt][i] = 0.f;

    for (int kt = 0; kt < 8; kt++) {
        const int k0 = kt * 64;
        __syncthreads();

        const float* kg = Kg + ((size_t)(b * T_ + k0)) * D_ + h * DK_;
        const float* vg = Vg + ((size_t)(b * T_ + k0)) * D_ + h * DK_;
        #pragma unroll
        for (int c = 0; c < 8; c++) {
            float4 kv = *(const float4*)(kg + (size_t)sr * D_ + sc + c * 4);
            float4 kt4;
            kt4.x = tf32f(kv.x); kt4.y = tf32f(kv.y);
            kt4.z = tf32f(kv.z); kt4.w = tf32f(kv.w);
            *(float4*)&Ks[sr * KS_STR + sc + c * 4] = kt4;
            float4 vv = *(const float4*)(vg + (size_t)sr * D_ + sc + c * 4);
            float4 vt4;
            vt4.x = tf32f(vv.x); vt4.y = tf32f(vv.y);
            vt4.z = tf32f(vv.z); vt4.w = tf32f(vv.w);
            *(float4*)&Vs[sr * VS_STR + sc + c * 4] = vt4;
        }
        if (tid < 127)
            bias_s[tid] = __ldg(&rel[(k0 - q0 - 63 + tid + 511) * 8 + h]);
        if (tid < 64)
            mask_s[tid] = __ldg(&kpm[b * T_ + k0 + tid]) ? -2e30f : 0.f;
        __syncthreads();

        float sacc[8][4];
        #pragma unroll
        for (int nt = 0; nt < 8; nt++)
            #pragma unroll
            for (int i = 0; i < 4; i++) sacc[nt][i] = 0.f;

        #pragma unroll
        for (int ks = 0; ks < 8; ks++) {
            #pragma unroll
            for (int nt = 0; nt < 8; nt++) {
                uint32_t b0 = __float_as_uint(Ks[(nt * 8 + r) * KS_STR + ks * 8 + cq]);
                uint32_t b1 = __float_as_uint(Ks[(nt * 8 + r) * KS_STR + ks * 8 + cq + 4]);
                mma_tf32(sacc[nt], qf[ks][0], qf[ks][1], qf[ks][2], qf[ks][3], b0, b1);
            }
        }

        const int rr0 = wm + r, rr1 = wm + r + 8;
        #pragma unroll
        for (int nt = 0; nt < 8; nt++) {
            const int cc = nt * 8 + 2 * cq;
            const float mk0 = mask_s[cc], mk1 = mask_s[cc + 1];
            sacc[nt][0] = fmaf(sacc[nt][0], 0.125f, bias_s[cc     - rr0 + 63] + mk0);
            sacc[nt][1] = fmaf(sacc[nt][1], 0.125f, bias_s[cc + 1 - rr0 + 63] + mk1);
            sacc[nt][2] = fmaf(sacc[nt][2], 0.125f, bias_s[cc     - rr1 + 63] + mk0);
            sacc[nt][3] = fmaf(sacc[nt][3], 0.125f, bias_s[cc + 1 - rr1 + 63] + mk1);
        }

        float rm0 = -1e30f, rm1 = -1e30f;
        #pragma unroll
        for (int nt = 0; nt < 8; nt++) {
            rm0 = fmaxf(rm0, fmaxf(sacc[nt][0], sacc[nt][1]));
            rm1 = fmaxf(rm1, fmaxf(sacc[nt][2], sacc[nt][3]));
        }
        rm0 = fmaxf(rm0, __shfl_xor_sync(0xffffffffu, rm0, 1));
        rm0 = fmaxf(rm0, __shfl_xor_sync(0xffffffffu, rm0, 2));
        rm1 = fmaxf(rm1, __shfl_xor_sync(0xffffffffu, rm1, 1));
        rm1 = fmaxf(rm1, __shfl_xor_sync(0xffffffffu, rm1, 2));

        const float mn0 = fmaxf(m0, rm0), mn1 = fmaxf(m1, rm1);
        const float al0 = __expf(m0 - mn0), al1 = __expf(m1 - mn1);
        m0 = mn0; m1 = mn1;

        float rs0 = 0.f, rs1 = 0.f;
        #pragma unroll
        for (int nt = 0; nt < 8; nt++) {
            sacc[nt][0] = __expf(sacc[nt][0] - mn0);
            sacc[nt][1] = __expf(sacc[nt][1] - mn0);
            sacc[nt][2] = __expf(sacc[nt][2] - mn1);
            sacc[nt][3] = __expf(sacc[nt][3] - mn1);
            rs0 += sacc[nt][0] + sacc[nt][1];
            rs1 += sacc[nt][2] + sacc[nt][3];
        }
        rs0 += __shfl_xor_sync(0xffffffffu, rs0, 1);
        rs0 += __shfl_xor_sync(0xffffffffu, rs0, 2);
        rs1 += __shfl_xor_sync(0xffffffffu, rs1, 1);
        rs1 += __shfl_xor_sync(0xffffffffu, rs1, 2);
        l0 = l0 * al0 + rs0;
        l1 = l1 * al1 + rs1;
        #pragma unroll
        for (int nt = 0; nt < 8; nt++) {
            oacc[nt][0] *= al0; oacc[nt][1] *= al0;
            oacc[nt][2] *= al1; oacc[nt][3] *= al1;
        }

        __syncthreads();

        #pragma unroll
        for (int nt = 0; nt < 8; nt++) {
            const int cc = nt * 8 + 2 * cq;
            float2 p0, p1;
            p0.x = tf32f(sacc[nt][0]); p0.y = tf32f(sacc[nt][1]);
            p1.x = tf32f(sacc[nt][2]); p1.y = tf32f(sacc[nt][3]);
            *(float2*)&Ks[rr0 * KS_STR + cc] = p0;
            *(float2*)&Ks[rr1 * KS_STR + cc] = p1;
        }
        __syncthreads();

        #pragma unroll
        for (int ks = 0; ks < 8; ks++) {
            uint32_t a0 = __float_as_uint(Ks[rr0 * KS_STR + ks * 8 + cq]);
            uint32_t a1 = __float_as_uint(Ks[rr1 * KS_STR + ks * 8 + cq]);
            uint32_t a2 = __float_as_uint(Ks[rr0 * KS_STR + ks * 8 + cq + 4]);
            uint32_t a3 = __float_as_uint(Ks[rr1 * KS_STR + ks * 8 + cq + 4]);
            #pragma unroll
            for (int nt = 0; nt < 8; nt++) {
                uint32_t b0 = __float_as_uint(Vs[(ks * 8 + cq)     * VS_STR + nt * 8 + r]);
                uint32_t b1 = __float_as_uint(Vs[(ks * 8 + cq + 4) * VS_STR + nt * 8 + r]);
                mma_tf32(oacc[nt], a0, a1, a2, a3, b0, b1);
            }
        }
    }

    const float inv0 = 1.f / l0, inv1 = 1.f / l1;
    const int row0 = b * T_ + q0 + wm + r;
    #pragma unroll
    for (int nt = 0; nt < 8; nt++) {
        const int col = h * DK_ + nt * 8 + 2 * cq;
        float2 o0, o1;
        o0.x = oacc[nt][0] * inv0; o0.y = oacc[nt][1] * inv0;
        o1.x = oacc[nt][2] * inv1; o1.y = oacc[nt][3] * inv1;
        *(float2*)(out + (size_t)row0 * D_ + col)       = o0;
        *(float2*)(out + (size_t)(row0 + 8) * D_ + col) = o1;
    }
}

// ============================================================================
extern "C" void kernel_launch(void* const* d_in, const int* in_sizes, int n_in,
                              void* d_out, int out_size)
{
    const float* x   = (const float*)d_in[0];
    const float* Wq  = (const float*)d_in[1];
    const float* bq  = (const float*)d_in[2];
    const float* Wk  = (const float*)d_in[3];
    const float* bk  = (const float*)d_in[4];
    const float* Wv  = (const float*)d_in[5];
    const float* bv  = (const float*)d_in[6];
    const float* Wo  = (const float*)d_in[7];
    const float* bo  = (const float*)d_in[8];
    const float* rel = (const float*)d_in[9];
    const unsigned int* kpm = (const unsigned int*)d_in[10];
    float* out = (float*)d_out;

    float *qp, *kp, *vp, *ap;
    cudaGetSymbolAddress((void**)&qp, g_q);
    cudaGetSymbolAddress((void**)&kp, g_k);
    cudaGetSymbolAddress((void**)&vp, g_v);
    cudaGetSymbolAddress((void**)&ap, g_att);

    dim3 qkv_grid(D_ / 128, M_ / 128, 3);   // (4, 128, 3)
    qkv_gemm<<<qkv_grid, 256>>>(x, Wq, bq, Wk, bk, Wv, bv, qp, kp, vp);

    dim3 at_grid(T_ / 64, B_ * H_);         // (8, 256)
    attn_tc<<<at_grid, 128>>>(qp, kp, vp, rel, kpm, ap);

    dim3 gemm_grid(D_ / 128, M_ / 128);     // (4, 128)
    out_gemm<<<gemm_grid, 256>>>(ap, Wo, bo, out);
}

// round 11
// speedup vs baseline: 3.0415x; 1.1193x over previous
#include <cuda_runtime.h>
#include <cstdint>

#define B_   32
#define T_   512
#define D_   512
#define H_   8
#define DK_  64
#define M_   (B_ * T_)   // 16384

// ---- scratch (no allocations allowed) ----
__device__ float g_q[M_ * D_];
__device__ float g_k[M_ * D_];
__device__ float g_v[M_ * D_];
__device__ float g_att[M_ * D_];

// ============================================================================
// tf32 helpers
// ============================================================================
__device__ __forceinline__ uint32_t f32_tf32(float x) {
    uint32_t u;
    asm("cvt.rna.tf32.f32 %0, %1;" : "=r"(u) : "f"(x));
    return u;
}
__device__ __forceinline__ float tf32f(float x) {
    uint32_t u = f32_tf32(x);
    return __uint_as_float(u);
}

__device__ __forceinline__ void mma_tf32(float c[4],
    uint32_t a0, uint32_t a1, uint32_t a2, uint32_t a3,
    uint32_t b0, uint32_t b1)
{
    asm volatile(
        "mma.sync.aligned.m16n8k8.row.col.f32.tf32.tf32.f32 "
        "{%0,%1,%2,%3}, {%4,%5,%6,%7}, {%8,%9}, {%0,%1,%2,%3};\n"
        : "+f"(c[0]), "+f"(c[1]), "+f"(c[2]), "+f"(c[3])
        : "r"(a0), "r"(a1), "r"(a2), "r"(a3), "r"(b0), "r"(b1));
}

// ============================================================================
// Projection GEMM via tf32 tensor cores.
// 128x128 block tile, BK=16, 256 threads = 8 warps (4m x 2n), warp tile
// 32x64 = 2 m-frags x 8 n-frags of m16n8k8.
// Smem tiles in NATURAL [row][k] layout, row stride 20 floats (16 + 4 pad):
//   - fragment loads: bank = (20*r + cq) mod 32 -> 32 distinct banks, CF.
//   - staging: no transpose; one STS.128 per half-row (4 per thread per slab).
// 2-stage double buffer, one __syncthreads per slab.
// ============================================================================
#define GST 20   // smem row stride in floats

__device__ __forceinline__ void gemm_tf32_body(
    const float* __restrict__ A, const float* __restrict__ W,
    const float* __restrict__ bias, float* __restrict__ C)
{
    __shared__ __align__(16) uint32_t As[2][128][GST];
    __shared__ __align__(16) uint32_t Bs[2][128][GST];

    const int m0  = blockIdx.y * 128;
    const int n0  = blockIdx.x * 128;
    const int tid = threadIdx.x;
    const int lane = tid & 31;
    const int warp = tid >> 5;
    const int wm0 = (warp >> 1) * 32;
    const int wn0 = (warp & 1) * 64;
    const int r   = lane >> 2;
    const int cq  = lane & 3;

    const int lr  = tid >> 2;          // staging rows lr, lr+64
    const int lc  = (tid & 3) << 2;    // staging k-chunk {0,4,8,12}

    const float* Ap = A + (size_t)(m0 + lr) * 512 + lc;
    const float* Wp = W + (size_t)(n0 + lr) * 512 + lc;
    const size_t half = (size_t)64 * 512;

    float acc[2][8][4];
    #pragma unroll
    for (int mt = 0; mt < 2; mt++)
        #pragma unroll
        for (int nt = 0; nt < 8; nt++)
            #pragma unroll
            for (int i = 0; i < 4; i++) acc[mt][nt][i] = 0.f;

    float4 a0, a1, w0, w1;

    a0 = *(const float4*)(Ap);
    a1 = *(const float4*)(Ap + half);
    w0 = *(const float4*)(Wp);
    w1 = *(const float4*)(Wp + half);
    {
        *(uint4*)&As[0][lr][lc] =
            make_uint4(f32_tf32(a0.x), f32_tf32(a0.y), f32_tf32(a0.z), f32_tf32(a0.w));
        *(uint4*)&As[0][lr + 64][lc] =
            make_uint4(f32_tf32(a1.x), f32_tf32(a1.y), f32_tf32(a1.z), f32_tf32(a1.w));
        *(uint4*)&Bs[0][lr][lc] =
            make_uint4(f32_tf32(w0.x), f32_tf32(w0.y), f32_tf32(w0.z), f32_tf32(w0.w));
        *(uint4*)&Bs[0][lr + 64][lc] =
            make_uint4(f32_tf32(w1.x), f32_tf32(w1.y), f32_tf32(w1.z), f32_tf32(w1.w));
    }
    __syncthreads();

    #pragma unroll 2
    for (int k0 = 0; k0 < 512; k0 += 16) {
        const int buf = (k0 >> 4) & 1;
        const bool has_next = (k0 + 16) < 512;

        if (has_next) {
            a0 = *(const float4*)(Ap + k0 + 16);
            a1 = *(const float4*)(Ap + half + k0 + 16);
            w0 = *(const float4*)(Wp + k0 + 16);
            w1 = *(const float4*)(Wp + half + k0 + 16);
        }

        // ---- compute slab k0 from buffer buf ([row][k], CF scalar loads) ----
        #pragma unroll
        for (int ks = 0; ks < 2; ks++) {
            const int kb = ks * 8;
            uint32_t af[2][4];
            #pragma unroll
            for (int mt = 0; mt < 2; mt++) {
                const int mb = wm0 + mt * 16;
                af[mt][0] = As[buf][mb + r]    [kb + cq];
                af[mt][1] = As[buf][mb + r + 8][kb + cq];
                af[mt][2] = As[buf][mb + r]    [kb + cq + 4];
                af[mt][3] = As[buf][mb + r + 8][kb + cq + 4];
            }
            uint32_t bf[8][2];
            #pragma unroll
            for (int nt = 0; nt < 8; nt++) {
                const int nb = wn0 + nt * 8;
                bf[nt][0] = Bs[buf][nb + r][kb + cq];
                bf[nt][1] = Bs[buf][nb + r][kb + cq + 4];
            }
            #pragma unroll
            for (int mt = 0; mt < 2; mt++)
                #pragma unroll
                for (int nt = 0; nt < 8; nt++)
                    mma_tf32(acc[mt][nt], af[mt][0], af[mt][1], af[mt][2], af[mt][3],
                             bf[nt][0], bf[nt][1]);
        }

        // ---- stage prefetched slab into the other buffer (vector stores) ----
        if (has_next) {
            const int nb = buf ^ 1;
            *(uint4*)&As[nb][lr][lc] =
                make_uint4(f32_tf32(a0.x), f32_tf32(a0.y), f32_tf32(a0.z), f32_tf32(a0.w));
            *(uint4*)&As[nb][lr + 64][lc] =
                make_uint4(f32_tf32(a1.x), f32_tf32(a1.y), f32_tf32(a1.z), f32_tf32(a1.w));
            *(uint4*)&Bs[nb][lr][lc] =
                make_uint4(f32_tf32(w0.x), f32_tf32(w0.y), f32_tf32(w0.z), f32_tf32(w0.w));
            *(uint4*)&Bs[nb][lr + 64][lc] =
                make_uint4(f32_tf32(w1.x), f32_tf32(w1.y), f32_tf32(w1.z), f32_tf32(w1.w));
        }
        __syncthreads();
    }

    #pragma unroll
    for (int nt = 0; nt < 8; nt++) {
        const int n = n0 + wn0 + nt * 8 + 2 * cq;
        const float2 bv = *(const float2*)(bias + n);
        #pragma unroll
        for (int mt = 0; mt < 2; mt++) {
            const int row = m0 + wm0 + mt * 16 + r;
            float2 o0, o1;
            o0.x = acc[mt][nt][0] + bv.x; o0.y = acc[mt][nt][1] + bv.y;
            o1.x = acc[mt][nt][2] + bv.x; o1.y = acc[mt][nt][3] + bv.y;
            *(float2*)(C + (size_t)row * 512 + n)       = o0;
            *(float2*)(C + (size_t)(row + 8) * 512 + n) = o1;
        }
    }
}

__global__ __launch_bounds__(256, 2) void qkv_gemm(
    const float* __restrict__ A,
    const float* __restrict__ Wq, const float* __restrict__ bq,
    const float* __restrict__ Wk, const float* __restrict__ bk,
    const float* __restrict__ Wv, const float* __restrict__ bv,
    float* __restrict__ Cq, float* __restrict__ Ck, float* __restrict__ Cv)
{
    const int z = blockIdx.z;
    const float* W    = (z == 0) ? Wq : (z == 1) ? Wk : Wv;
    const float* bias = (z == 0) ? bq : (z == 1) ? bk : bv;
    float*       C    = (z == 0) ? Cq : (z == 1) ? Ck : Cv;
    gemm_tf32_body(A, W, bias, C);
}

__global__ __launch_bounds__(256, 2) void out_gemm(
    const float* __restrict__ A, const float* __restrict__ W,
    const float* __restrict__ bias, float* __restrict__ C)
{
    gemm_tf32_body(A, W, bias, C);
}

// ============================================================================
// Tensor-core flash attention (unchanged from passing round 9).
// ============================================================================
#define KS_STR 68
#define VS_STR 72

__global__ __launch_bounds__(128) void attn_tc(
    const float* __restrict__ Q, const float* __restrict__ Kg,
    const float* __restrict__ Vg,
    const float* __restrict__ rel,           // [1023, 8]
    const unsigned int* __restrict__ kpm,    // [B, T], nonzero word => masked
    float* __restrict__ out)                 // [B, T, H, DK]
{
    __shared__ __align__(16) float Ks[64 * KS_STR];   // K tile, then P
    __shared__ __align__(16) float Vs[64 * VS_STR];   // V tile (Q staging at start)
    __shared__ float bias_s[128];
    __shared__ float mask_s[64];

    const int bh = blockIdx.y;
    const int b  = bh >> 3;
    const int h  = bh & 7;
    const int q0 = blockIdx.x * 64;
    const int tid  = threadIdx.x;
    const int lane = tid & 31;
    const int warp = tid >> 5;
    const int r  = lane >> 2;
    const int cq = lane & 3;
    const int wm = warp * 16;

    const int sr = tid >> 1;
    const int sc = (tid & 1) * 32;

    {
        const float* qg = Q + ((size_t)(b * T_ + q0)) * D_ + h * DK_;
        #pragma unroll
        for (int c = 0; c < 8; c++) {
            float4 v = *(const float4*)(qg + (size_t)sr * D_ + sc + c * 4);
            *(float4*)&Vs[sr * VS_STR + sc + c * 4] = v;
        }
    }
    __syncthreads();
    uint32_t qf[8][4];
    #pragma unroll
    for (int ks = 0; ks < 8; ks++) {
        qf[ks][0] = f32_tf32(Vs[(wm + r)     * VS_STR + ks * 8 + cq]);
        qf[ks][1] = f32_tf32(Vs[(wm + r + 8) * VS_STR + ks * 8 + cq]);
        qf[ks][2] = f32_tf32(Vs[(wm + r)     * VS_STR + ks * 8 + cq + 4]);
        qf[ks][3] = f32_tf32(Vs[(wm + r + 8) * VS_STR + ks * 8 + cq + 4]);
    }

    float m0 = -1e30f, m1 = -1e30f, l0 = 0.f, l1 = 0.f;
    float oacc[8][4];
    #pragma unroll
    for (int nt = 0; nt < 8; nt++)
        #pragma unroll
        for (int i = 0; i < 4; i++) oacc[nt][i] = 0.f;

    for (int kt = 0; kt < 8; kt++) {
        const int k0 = kt * 64;
        __syncthreads();

        const float* kg = Kg + ((size_t)(b * T_ + k0)) * D_ + h * DK_;
        const float* vg = Vg + ((size_t)(b * T_ + k0)) * D_ + h * DK_;
        #pragma unroll
        for (int c = 0; c < 8; c++) {
            float4 kv = *(const float4*)(kg + (size_t)sr * D_ + sc + c * 4);
            float4 kt4;
            kt4.x = tf32f(kv.x); kt4.y = tf32f(kv.y);
            kt4.z = tf32f(kv.z); kt4.w = tf32f(kv.w);
            *(float4*)&Ks[sr * KS_STR + sc + c * 4] = kt4;
            float4 vv = *(const float4*)(vg + (size_t)sr * D_ + sc + c * 4);
            float4 vt4;
            vt4.x = tf32f(vv.x); vt4.y = tf32f(vv.y);
            vt4.z = tf32f(vv.z); vt4.w = tf32f(vv.w);
            *(float4*)&Vs[sr * VS_STR + sc + c * 4] = vt4;
        }
        if (tid < 127)
            bias_s[tid] = __ldg(&rel[(k0 - q0 - 63 + tid + 511) * 8 + h]);
        if (tid < 64)
            mask_s[tid] = __ldg(&kpm[b * T_ + k0 + tid]) ? -2e30f : 0.f;
        __syncthreads();

        float sacc[8][4];
        #pragma unroll
        for (int nt = 0; nt < 8; nt++)
            #pragma unroll
            for (int i = 0; i < 4; i++) sacc[nt][i] = 0.f;

        #pragma unroll
        for (int ks = 0; ks < 8; ks++) {
            #pragma unroll
            for (int nt = 0; nt < 8; nt++) {
                uint32_t b0 = __float_as_uint(Ks[(nt * 8 + r) * KS_STR + ks * 8 + cq]);
                uint32_t b1 = __float_as_uint(Ks[(nt * 8 + r) * KS_STR + ks * 8 + cq + 4]);
                mma_tf32(sacc[nt], qf[ks][0], qf[ks][1], qf[ks][2], qf[ks][3], b0, b1);
            }
        }

        const int rr0 = wm + r, rr1 = wm + r + 8;
        #pragma unroll
        for (int nt = 0; nt < 8; nt++) {
            const int cc = nt * 8 + 2 * cq;
            const float mk0 = mask_s[cc], mk1 = mask_s[cc + 1];
            sacc[nt][0] = fmaf(sacc[nt][0], 0.125f, bias_s[cc     - rr0 + 63] + mk0);
            sacc[nt][1] = fmaf(sacc[nt][1], 0.125f, bias_s[cc + 1 - rr0 + 63] + mk1);
            sacc[nt][2] = fmaf(sacc[nt][2], 0.125f, bias_s[cc     - rr1 + 63] + mk0);
            sacc[nt][3] = fmaf(sacc[nt][3], 0.125f, bias_s[cc + 1 - rr1 + 63] + mk1);
        }

        float rm0 = -1e30f, rm1 = -1e30f;
        #pragma unroll
        for (int nt = 0; nt < 8; nt++) {
            rm0 = fmaxf(rm0, fmaxf(sacc[nt][0], sacc[nt][1]));
            rm1 = fmaxf(rm1, fmaxf(sacc[nt][2], sacc[nt][3]));
        }
        rm0 = fmaxf(rm0, __shfl_xor_sync(0xffffffffu, rm0, 1));
        rm0 = fmaxf(rm0, __shfl_xor_sync(0xffffffffu, rm0, 2));
        rm1 = fmaxf(rm1, __shfl_xor_sync(0xffffffffu, rm1, 1));
        rm1 = fmaxf(rm1, __shfl_xor_sync(0xffffffffu, rm1, 2));

        const float mn0 = fmaxf(m0, rm0), mn1 = fmaxf(m1, rm1);
        const float al0 = __expf(m0 - mn0), al1 = __expf(m1 - mn1);
        m0 = mn0; m1 = mn1;

        float rs0 = 0.f, rs1 = 0.f;
        #pragma unroll
        for (int nt = 0; nt < 8; nt++) {
            sacc[nt][0] = __expf(sacc[nt][0] - mn0);
            sacc[nt][1] = __expf(sacc[nt][1] - mn0);
            sacc[nt][2] = __expf(sacc[nt][2] - mn1);
            sacc[nt][3] = __expf(sacc[nt][3] - mn1);
            rs0 += sacc[nt][0] + sacc[nt][1];
            rs1 += sacc[nt][2] + sacc[nt][3];
        }
        rs0 += __shfl_xor_sync(0xffffffffu, rs0, 1);
        rs0 += __shfl_xor_sync(0xffffffffu, rs0, 2);
        rs1 += __shfl_xor_sync(0xffffffffu, rs1, 1);
        rs1 += __shfl_xor_sync(0xffffffffu, rs1, 2);
        l0 = l0 * al0 + rs0;
        l1 = l1 * al1 + rs1;
        #pragma unroll
        for (int nt = 0; nt < 8; nt++) {
            oacc[nt][0] *= al0; oacc[nt][1] *= al0;
            oacc[nt][2] *= al1; oacc[nt][3] *= al1;
        }

        __syncthreads();

        #pragma unroll
        for (int nt = 0; nt < 8; nt++) {
            const int cc = nt * 8 + 2 * cq;
            float2 p0, p1;
            p0.x = tf32f(sacc[nt][0]); p0.y = tf32f(sacc[nt][1]);
            p1.x = tf32f(sacc[nt][2]); p1.y = tf32f(sacc[nt][3]);
            *(float2*)&Ks[rr0 * KS_STR + cc] = p0;
            *(float2*)&Ks[rr1 * KS_STR + cc] = p1;
        }
        __syncthreads();

        #pragma unroll
        for (int ks = 0; ks < 8; ks++) {
            uint32_t a0 = __float_as_uint(Ks[rr0 * KS_STR + ks * 8 + cq]);
            uint32_t a1 = __float_as_uint(Ks[rr1 * KS_STR + ks * 8 + cq]);
            uint32_t a2 = __float_as_uint(Ks[rr0 * KS_STR + ks * 8 + cq + 4]);
            uint32_t a3 = __float_as_uint(Ks[rr1 * KS_STR + ks * 8 + cq + 4]);
            #pragma unroll
            for (int nt = 0; nt < 8; nt++) {
                uint32_t b0 = __float_as_uint(Vs[(ks * 8 + cq)     * VS_STR + nt * 8 + r]);
                uint32_t b1 = __float_as_uint(Vs[(ks * 8 + cq + 4) * VS_STR + nt * 8 + r]);
                mma_tf32(oacc[nt], a0, a1, a2, a3, b0, b1);
            }
        }
    }

    const float inv0 = 1.f / l0, inv1 = 1.f / l1;
    const int row0 = b * T_ + q0 + wm + r;
    #pragma unroll
    for (int nt = 0; nt < 8; nt++) {
        const int col = h * DK_ + nt * 8 + 2 * cq;
        float2 o0, o1;
        o0.x = oacc[nt][0] * inv0; o0.y = oacc[nt][1] * inv0;
        o1.x = oacc[nt][2] * inv1; o1.y = oacc[nt][3] * inv1;
        *(float2*)(out + (size_t)row0 * D_ + col)       = o0;
        *(float2*)(out + (size_t)(row0 + 8) * D_ + col) = o1;
    }
}

// ============================================================================
extern "C" void kernel_launch(void* const* d_in, const int* in_sizes, int n_in,
                              void* d_out, int out_size)
{
    const float* x   = (const float*)d_in[0];
    const float* Wq  = (const float*)d_in[1];
    const float* bq  = (const float*)d_in[2];
    const float* Wk  = (const float*)d_in[3];
    const float* bk  = (const float*)d_in[4];
    const float* Wv  = (const float*)d_in[5];
    const float* bv  = (const float*)d_in[6];
    const float* Wo  = (const float*)d_in[7];
    const float* bo  = (const float*)d_in[8];
    const float* rel = (const float*)d_in[9];
    const unsigned int* kpm = (const unsigned int*)d_in[10];
    float* out = (float*)d_out;

    float *qp, *kp, *vp, *ap;
    cudaGetSymbolAddress((void**)&qp, g_q);
    cudaGetSymbolAddress((void**)&kp, g_k);
    cudaGetSymbolAddress((void**)&vp, g_v);
    cudaGetSymbolAddress((void**)&ap, g_att);

    dim3 qkv_grid(D_ / 128, M_ / 128, 3);   // (4, 128, 3)
    qkv_gemm<<<qkv_grid, 256>>>(x, Wq, bq, Wk, bk, Wv, bv, qp, kp, vp);

    dim3 at_grid(T_ / 64, B_ * H_);         // (8, 256)
    attn_tc<<<at_grid, 128>>>(qp, kp, vp, rel, kpm, ap);

    dim3 gemm_grid(D_ / 128, M_ / 128);     // (4, 128)
    out_gemm<<<gemm_grid, 256>>>(ap, Wo, bo, out);
}

// round 13
// speedup vs baseline: 3.6844x; 1.2114x over previous
#include <cuda_runtime.h>
#include <cstdint>

#define B_   32
#define T_   512
#define D_   512
#define H_   8
#define DK_  64
#define M_   (B_ * T_)   // 16384

// ---- scratch (no allocations allowed) ----
__device__ float g_q[M_ * D_];
__device__ float g_k[M_ * D_];
__device__ float g_v[M_ * D_];
__device__ float g_att[M_ * D_];

// ============================================================================
// tf32 helpers
// ============================================================================
__device__ __forceinline__ uint32_t f32_tf32(float x) {
    uint32_t u;
    asm("cvt.rna.tf32.f32 %0, %1;" : "=r"(u) : "f"(x));
    return u;
}
__device__ __forceinline__ float tf32f(float x) {
    uint32_t u = f32_tf32(x);
    return __uint_as_float(u);
}

__device__ __forceinline__ void mma_tf32(float c[4],
    uint32_t a0, uint32_t a1, uint32_t a2, uint32_t a3,
    uint32_t b0, uint32_t b1)
{
    asm volatile(
        "mma.sync.aligned.m16n8k8.row.col.f32.tf32.tf32.f32 "
        "{%0,%1,%2,%3}, {%4,%5,%6,%7}, {%8,%9}, {%0,%1,%2,%3};\n"
        : "+f"(c[0]), "+f"(c[1]), "+f"(c[2]), "+f"(c[3])
        : "r"(a0), "r"(a1), "r"(a2), "r"(a3), "r"(b0), "r"(b1));
}

// ============================================================================
// Projection GEMM via tf32 tensor cores (R11 passing version, unchanged).
// 128x128 block tile, BK=16, 256 threads = 8 warps (4m x 2n).
// Smem [row][k] stride 20 floats -> conflict-free fragment loads, STS.128
// staging, 2-stage double buffer.
// ============================================================================
#define GST 20

__device__ __forceinline__ void gemm_tf32_body(
    const float* __restrict__ A, const float* __restrict__ W,
    const float* __restrict__ bias, float* __restrict__ C)
{
    __shared__ __align__(16) uint32_t As[2][128][GST];
    __shared__ __align__(16) uint32_t Bs[2][128][GST];

    const int m0  = blockIdx.y * 128;
    const int n0  = blockIdx.x * 128;
    const int tid = threadIdx.x;
    const int lane = tid & 31;
    const int warp = tid >> 5;
    const int wm0 = (warp >> 1) * 32;
    const int wn0 = (warp & 1) * 64;
    const int r   = lane >> 2;
    const int cq  = lane & 3;

    const int lr  = tid >> 2;
    const int lc  = (tid & 3) << 2;

    const float* Ap = A + (size_t)(m0 + lr) * 512 + lc;
    const float* Wp = W + (size_t)(n0 + lr) * 512 + lc;
    const size_t half = (size_t)64 * 512;

    float acc[2][8][4];
    #pragma unroll
    for (int mt = 0; mt < 2; mt++)
        #pragma unroll
        for (int nt = 0; nt < 8; nt++)
            #pragma unroll
            for (int i = 0; i < 4; i++) acc[mt][nt][i] = 0.f;

    float4 a0, a1, w0, w1;

    a0 = *(const float4*)(Ap);
    a1 = *(const float4*)(Ap + half);
    w0 = *(const float4*)(Wp);
    w1 = *(const float4*)(Wp + half);
    {
        *(uint4*)&As[0][lr][lc] =
            make_uint4(f32_tf32(a0.x), f32_tf32(a0.y), f32_tf32(a0.z), f32_tf32(a0.w));
        *(uint4*)&As[0][lr + 64][lc] =
            make_uint4(f32_tf32(a1.x), f32_tf32(a1.y), f32_tf32(a1.z), f32_tf32(a1.w));
        *(uint4*)&Bs[0][lr][lc] =
            make_uint4(f32_tf32(w0.x), f32_tf32(w0.y), f32_tf32(w0.z), f32_tf32(w0.w));
        *(uint4*)&Bs[0][lr + 64][lc] =
            make_uint4(f32_tf32(w1.x), f32_tf32(w1.y), f32_tf32(w1.z), f32_tf32(w1.w));
    }
    __syncthreads();

    #pragma unroll 2
    for (int k0 = 0; k0 < 512; k0 += 16) {
        const int buf = (k0 >> 4) & 1;
        const bool has_next = (k0 + 16) < 512;

        if (has_next) {
            a0 = *(const float4*)(Ap + k0 + 16);
            a1 = *(const float4*)(Ap + half + k0 + 16);
            w0 = *(const float4*)(Wp + k0 + 16);
            w1 = *(const float4*)(Wp + half + k0 + 16);
        }

        #pragma unroll
        for (int ks = 0; ks < 2; ks++) {
            const int kb = ks * 8;
            uint32_t af[2][4];
            #pragma unroll
            for (int mt = 0; mt < 2; mt++) {
                const int mb = wm0 + mt * 16;
                af[mt][0] = As[buf][mb + r]    [kb + cq];
                af[mt][1] = As[buf][mb + r + 8][kb + cq];
                af[mt][2] = As[buf][mb + r]    [kb + cq + 4];
                af[mt][3] = As[buf][mb + r + 8][kb + cq + 4];
            }
            uint32_t bf[8][2];
            #pragma unroll
            for (int nt = 0; nt < 8; nt++) {
                const int nb = wn0 + nt * 8;
                bf[nt][0] = Bs[buf][nb + r][kb + cq];
                bf[nt][1] = Bs[buf][nb + r][kb + cq + 4];
            }
            #pragma unroll
            for (int mt = 0; mt < 2; mt++)
                #pragma unroll
                for (int nt = 0; nt < 8; nt++)
                    mma_tf32(acc[mt][nt], af[mt][0], af[mt][1], af[mt][2], af[mt][3],
                             bf[nt][0], bf[nt][1]);
        }

        if (has_next) {
            const int nb = buf ^ 1;
            *(uint4*)&As[nb][lr][lc] =
                make_uint4(f32_tf32(a0.x), f32_tf32(a0.y), f32_tf32(a0.z), f32_tf32(a0.w));
            *(uint4*)&As[nb][lr + 64][lc] =
                make_uint4(f32_tf32(a1.x), f32_tf32(a1.y), f32_tf32(a1.z), f32_tf32(a1.w));
            *(uint4*)&Bs[nb][lr][lc] =
                make_uint4(f32_tf32(w0.x), f32_tf32(w0.y), f32_tf32(w0.z), f32_tf32(w0.w));
            *(uint4*)&Bs[nb][lr + 64][lc] =
                make_uint4(f32_tf32(w1.x), f32_tf32(w1.y), f32_tf32(w1.z), f32_tf32(w1.w));
        }
        __syncthreads();
    }

    #pragma unroll
    for (int nt = 0; nt < 8; nt++) {
        const int n = n0 + wn0 + nt * 8 + 2 * cq;
        const float2 bv = *(const float2*)(bias + n);
        #pragma unroll
        for (int mt = 0; mt < 2; mt++) {
            const int row = m0 + wm0 + mt * 16 + r;
            float2 o0, o1;
            o0.x = acc[mt][nt][0] + bv.x; o0.y = acc[mt][nt][1] + bv.y;
            o1.x = acc[mt][nt][2] + bv.x; o1.y = acc[mt][nt][3] + bv.y;
            *(float2*)(C + (size_t)row * 512 + n)       = o0;
            *(float2*)(C + (size_t)(row + 8) * 512 + n) = o1;
        }
    }
}

__global__ __launch_bounds__(256, 2) void qkv_gemm(
    const float* __restrict__ A,
    const float* __restrict__ Wq, const float* __restrict__ bq,
    const float* __restrict__ Wk, const float* __restrict__ bk,
    const float* __restrict__ Wv, const float* __restrict__ bv,
    float* __restrict__ Cq, float* __restrict__ Ck, float* __restrict__ Cv)
{
    const int z = blockIdx.z;
    const float* W    = (z == 0) ? Wq : (z == 1) ? Wk : Wv;
    const float* bias = (z == 0) ? bq : (z == 1) ? bk : bv;
    float*       C    = (z == 0) ? Cq : (z == 1) ? Ck : Cv;
    gemm_tf32_body(A, W, bias, C);
}

__global__ __launch_bounds__(256, 2) void out_gemm(
    const float* __restrict__ A, const float* __restrict__ W,
    const float* __restrict__ bias, float* __restrict__ C)
{
    gemm_tf32_body(A, W, bias, C);
}

// ============================================================================
// Tensor-core flash attention, 128-query tile, register-resident P.
// 256 threads = 8 warps; warp w owns query rows [w*16, w*16+16) x 64 keys.
//  - Q fragments loaded once from gmem into registers (tf32).
//  - K tile [key][d] stride 68, V tile [key][d] stride 72 (CF frag reads).
//  - P stays in registers: C-fragment -> A-fragment via quad shuffles
//    (col ks*8+j lives in lane (lane&~3)|(j>>1), elem j&1).
//  - 2 syncthreads per key tile (stage guard + stage complete).
// ============================================================================
#define KS_STR 68
#define VS_STR 72

__global__ __launch_bounds__(256, 2) void attn_tc(
    const float* __restrict__ Q, const float* __restrict__ Kg,
    const float* __restrict__ Vg,
    const float* __restrict__ rel,           // [1023, 8]
    const unsigned int* __restrict__ kpm,    // [B, T], nonzero word => masked
    float* __restrict__ out)                 // [B, T, H, DK]
{
    __shared__ __align__(16) float Ks[64 * KS_STR];
    __shared__ __align__(16) float Vs[64 * VS_STR];
    __shared__ float bias_s[192];
    __shared__ float mask_s[64];

    const int bh = blockIdx.y;
    const int b  = bh >> 3;
    const int h  = bh & 7;
    const int q0 = blockIdx.x * 128;
    const int tid  = threadIdx.x;
    const int lane = tid & 31;
    const int warp = tid >> 5;
    const int r  = lane >> 2;     // 0..7
    const int cq = lane & 3;      // 0..3
    const int wm = warp * 16;     // query stripe base (local, 0..112)

    const int sr = tid >> 2;            // staging row 0..63
    const int sc = (tid & 3) * 16;      // staging col chunk

    // ---- Q fragments straight from gmem (one time) ----
    const float* qg = Q + ((size_t)(b * T_ + q0)) * D_ + h * DK_;
    uint32_t qf[8][4];
    #pragma unroll
    for (int ks = 0; ks < 8; ks++) {
        qf[ks][0] = f32_tf32(qg[(size_t)(wm + r)     * D_ + ks * 8 + cq]);
        qf[ks][1] = f32_tf32(qg[(size_t)(wm + r + 8) * D_ + ks * 8 + cq]);
        qf[ks][2] = f32_tf32(qg[(size_t)(wm + r)     * D_ + ks * 8 + cq + 4]);
        qf[ks][3] = f32_tf32(qg[(size_t)(wm + r + 8) * D_ + ks * 8 + cq + 4]);
    }

    float m0 = -1e30f, m1 = -1e30f, l0 = 0.f, l1 = 0.f;
    float oacc[8][4];
    #pragma unroll
    for (int nt = 0; nt < 8; nt++)
        #pragma unroll
        for (int i = 0; i < 4; i++) oacc[nt][i] = 0.f;

    const int srcA = (lane & ~3) | (cq >> 1);   // shuffle src for cols ks*8+cq
    const int srcB = srcA + 2;                  // shuffle src for cols ks*8+cq+4
    const bool odd = (cq & 1);

    for (int kt = 0; kt < 8; kt++) {
        const int k0 = kt * 64;
        __syncthreads();   // prior tile's Ks/Vs reads complete

        // ---- stage K (stride 68) / V (stride 72), tf32-rounded ----
        const float* kg = Kg + ((size_t)(b * T_ + k0)) * D_ + h * DK_;
        const float* vg = Vg + ((size_t)(b * T_ + k0)) * D_ + h * DK_;
        #pragma unroll
        for (int c = 0; c < 4; c++) {
            float4 kv = *(const float4*)(kg + (size_t)sr * D_ + sc + c * 4);
            float4 kt4;
            kt4.x = tf32f(kv.x); kt4.y = tf32f(kv.y);
            kt4.z = tf32f(kv.z); kt4.w = tf32f(kv.w);
            *(float4*)&Ks[sr * KS_STR + sc + c * 4] = kt4;
            float4 vv = *(const float4*)(vg + (size_t)sr * D_ + sc + c * 4);
            float4 vt4;
            vt4.x = tf32f(vv.x); vt4.y = tf32f(vv.y);
            vt4.z = tf32f(vv.z); vt4.w = tf32f(vv.w);
            *(float4*)&Vs[sr * VS_STR + sc + c * 4] = vt4;
        }
        // bias LUT: diff = k - q in [k0-q0-127, k0-q0+63] -> 191 entries
        if (tid < 191)
            bias_s[tid] = __ldg(&rel[(k0 - q0 - 127 + tid + 511) * 8 + h]);
        if (tid < 64)
            mask_s[tid] = __ldg(&kpm[b * T_ + k0 + tid]) ? -2e30f : 0.f;
        __syncthreads();

        // ---- S = Q K^T ----
        float sacc[8][4];
        #pragma unroll
        for (int nt = 0; nt < 8; nt++)
            #pragma unroll
            for (int i = 0; i < 4; i++) sacc[nt][i] = 0.f;

        #pragma unroll
        for (int ks = 0; ks < 8; ks++) {
            #pragma unroll
            for (int nt = 0; nt < 8; nt++) {
                uint32_t b0 = __float_as_uint(Ks[(nt * 8 + r) * KS_STR + ks * 8 + cq]);
                uint32_t b1 = __float_as_uint(Ks[(nt * 8 + r) * KS_STR + ks * 8 + cq + 4]);
                mma_tf32(sacc[nt], qf[ks][0], qf[ks][1], qf[ks][2], qf[ks][3], b0, b1);
            }
        }

        // ---- scale + bias + mask (f32) ----
        const int rr0 = wm + r, rr1 = wm + r + 8;
        #pragma unroll
        for (int nt = 0; nt < 8; nt++) {
            const int cc = nt * 8 + 2 * cq;
            const float mk0 = mask_s[cc], mk1 = mask_s[cc + 1];
            sacc[nt][0] = fmaf(sacc[nt][0], 0.125f, bias_s[cc     - rr0 + 127] + mk0);
            sacc[nt][1] = fmaf(sacc[nt][1], 0.125f, bias_s[cc + 1 - rr0 + 127] + mk1);
            sacc[nt][2] = fmaf(sacc[nt][2], 0.125f, bias_s[cc     - rr1 + 127] + mk0);
            sacc[nt][3] = fmaf(sacc[nt][3], 0.125f, bias_s[cc + 1 - rr1 + 127] + mk1);
        }

        // ---- online softmax (rows r / r+8, quad reduction) ----
        float rm0 = -1e30f, rm1 = -1e30f;
        #pragma unroll
        for (int nt = 0; nt < 8; nt++) {
            rm0 = fmaxf(rm0, fmaxf(sacc[nt][0], sacc[nt][1]));
            rm1 = fmaxf(rm1, fmaxf(sacc[nt][2], sacc[nt][3]));
        }
        rm0 = fmaxf(rm0, __shfl_xor_sync(0xffffffffu, rm0, 1));
        rm0 = fmaxf(rm0, __shfl_xor_sync(0xffffffffu, rm0, 2));
        rm1 = fmaxf(rm1, __shfl_xor_sync(0xffffffffu, rm1, 1));
        rm1 = fmaxf(rm1, __shfl_xor_sync(0xffffffffu, rm1, 2));

        const float mn0 = fmaxf(m0, rm0), mn1 = fmaxf(m1, rm1);
        const float al0 = __expf(m0 - mn0), al1 = __expf(m1 - mn1);
        m0 = mn0; m1 = mn1;

        float rs0 = 0.f, rs1 = 0.f;
        #pragma unroll
        for (int nt = 0; nt < 8; nt++) {
            sacc[nt][0] = __expf(sacc[nt][0] - mn0);
            sacc[nt][1] = __expf(sacc[nt][1] - mn0);
            sacc[nt][2] = __expf(sacc[nt][2] - mn1);
            sacc[nt][3] = __expf(sacc[nt][3] - mn1);
            rs0 += sacc[nt][0] + sacc[nt][1];
            rs1 += sacc[nt][2] + sacc[nt][3];
        }
        rs0 += __shfl_xor_sync(0xffffffffu, rs0, 1);
        rs0 += __shfl_xor_sync(0xffffffffu, rs0, 2);
        rs1 += __shfl_xor_sync(0xffffffffu, rs1, 1);
        rs1 += __shfl_xor_sync(0xffffffffu, rs1, 2);
        l0 = l0 * al0 + rs0;
        l1 = l1 * al1 + rs1;
        #pragma unroll
        for (int nt = 0; nt < 8; nt++) {
            oacc[nt][0] *= al0; oacc[nt][1] *= al0;
            oacc[nt][2] *= al1; oacc[nt][3] *= al1;
            // pre-round P to tf32 for the PV MMA
            sacc[nt][0] = tf32f(sacc[nt][0]);
            sacc[nt][1] = tf32f(sacc[nt][1]);
            sacc[nt][2] = tf32f(sacc[nt][2]);
            sacc[nt][3] = tf32f(sacc[nt][3]);
        }

        // ---- O += P V ; P A-fragments via quad shuffles ----
        #pragma unroll
        for (int ks = 0; ks < 8; ks++) {
            // cols ks*8+cq (a0: row r, a1: row r+8)
            float vA0 = __shfl_sync(0xffffffffu, sacc[ks][0], srcA);
            float vA1 = __shfl_sync(0xffffffffu, sacc[ks][1], srcA);
            float vA2 = __shfl_sync(0xffffffffu, sacc[ks][2], srcA);
            float vA3 = __shfl_sync(0xffffffffu, sacc[ks][3], srcA);
            // cols ks*8+cq+4 (a2: row r, a3: row r+8)
            float vB0 = __shfl_sync(0xffffffffu, sacc[ks][0], srcB);
            float vB1 = __shfl_sync(0xffffffffu, sacc[ks][1], srcB);
            float vB2 = __shfl_sync(0xffffffffu, sacc[ks][2], srcB);
            float vB3 = __shfl_sync(0xffffffffu, sacc[ks][3], srcB);
            uint32_t a0 = __float_as_uint(odd ? vA1 : vA0);
            uint32_t a1 = __float_as_uint(odd ? vA3 : vA2);
            uint32_t a2 = __float_as_uint(odd ? vB1 : vB0);
            uint32_t a3 = __float_as_uint(odd ? vB3 : vB2);
            #pragma unroll
            for (int nt = 0; nt < 8; nt++) {
                uint32_t b0 = __float_as_uint(Vs[(ks * 8 + cq)     * VS_STR + nt * 8 + r]);
                uint32_t b1 = __float_as_uint(Vs[(ks * 8 + cq + 4) * VS_STR + nt * 8 + r]);
                mma_tf32(oacc[nt], a0, a1, a2, a3, b0, b1);
            }
        }
    }

    // ---- epilogue: normalize and store ----
    const float inv0 = 1.f / l0, inv1 = 1.f / l1;
    const int row0 = b * T_ + q0 + wm + r;
    #pragma unroll
    for (int nt = 0; nt < 8; nt++) {
        const int col = h * DK_ + nt * 8 + 2 * cq;
        float2 o0, o1;
        o0.x = oacc[nt][0] * inv0; o0.y = oacc[nt][1] * inv0;
        o1.x = oacc[nt][2] * inv1; o1.y = oacc[nt][3] * inv1;
        *(float2*)(out + (size_t)row0 * D_ + col)       = o0;
        *(float2*)(out + (size_t)(row0 + 8) * D_ + col) = o1;
    }
}

// ============================================================================
extern "C" void kernel_launch(void* const* d_in, const int* in_sizes, int n_in,
                              void* d_out, int out_size)
{
    const float* x   = (const float*)d_in[0];
    const float* Wq  = (const float*)d_in[1];
    const float* bq  = (const float*)d_in[2];
    const float* Wk  = (const float*)d_in[3];
    const float* bk  = (const float*)d_in[4];
    const float* Wv  = (const float*)d_in[5];
    const float* bv  = (const float*)d_in[6];
    const float* Wo  = (const float*)d_in[7];
    const float* bo  = (const float*)d_in[8];
    const float* rel = (const float*)d_in[9];
    const unsigned int* kpm = (const unsigned int*)d_in[10];
    float* out = (float*)d_out;

    float *qp, *kp, *vp, *ap;
    cudaGetSymbolAddress((void**)&qp, g_q);
    cudaGetSymbolAddress((void**)&kp, g_k);
    cudaGetSymbolAddress((void**)&vp, g_v);
    cudaGetSymbolAddress((void**)&ap, g_att);

    dim3 qkv_grid(D_ / 128, M_ / 128, 3);   // (4, 128, 3)
    qkv_gemm<<<qkv_grid, 256>>>(x, Wq, bq, Wk, bk, Wv, bv, qp, kp, vp);

    dim3 at_grid(T_ / 128, B_ * H_);        // (4, 256)
    attn_tc<<<at_grid, 256>>>(qp, kp, vp, rel, kpm, ap);

    dim3 gemm_grid(D_ / 128, M_ / 128);     // (4, 128)
    out_gemm<<<gemm_grid, 256>>>(ap, Wo, bo, out);
}

// round 14
// speedup vs baseline: 3.7476x; 1.0171x over previous
#include <cuda_runtime.h>
#include <cstdint>

#define B_   32
#define T_   512
#define D_   512
#define H_   8
#define DK_  64
#define M_   (B_ * T_)   // 16384

// ---- scratch (no allocations allowed) ----
__device__ float g_q[M_ * D_];
__device__ float g_k[M_ * D_];
__device__ float g_v[M_ * D_];
__device__ float g_att[M_ * D_];

// ============================================================================
// tf32 helpers
// ============================================================================
__device__ __forceinline__ uint32_t f32_tf32(float x) {
    uint32_t u;
    asm("cvt.rna.tf32.f32 %0, %1;" : "=r"(u) : "f"(x));
    return u;
}
__device__ __forceinline__ float tf32f(float x) {
    uint32_t u = f32_tf32(x);
    return __uint_as_float(u);
}

__device__ __forceinline__ void mma_tf32(float c[4],
    uint32_t a0, uint32_t a1, uint32_t a2, uint32_t a3,
    uint32_t b0, uint32_t b1)
{
    asm volatile(
        "mma.sync.aligned.m16n8k8.row.col.f32.tf32.tf32.f32 "
        "{%0,%1,%2,%3}, {%4,%5,%6,%7}, {%8,%9}, {%0,%1,%2,%3};\n"
        : "+f"(c[0]), "+f"(c[1]), "+f"(c[2]), "+f"(c[3])
        : "r"(a0), "r"(a1), "r"(a2), "r"(a3), "r"(b0), "r"(b1));
}

// ============================================================================
// Projection GEMM via tf32 tensor cores.
// 128x128 block tile, BK=16, 128 threads = 4 warps (2m x 2n), warp tile
// 64x64 = 4 m-frags x 8 n-frags of m16n8k8  ->  1.0 frag-loads per MMA.
// Smem [row][k] stride 20 floats (CF fragment loads: banks 20r+cq distinct),
// STS.128 staging, 2-stage double buffer, one __syncthreads per slab.
// ============================================================================
#define GST 20

__device__ __forceinline__ void gemm_tf32_body(
    const float* __restrict__ A, const float* __restrict__ W,
    const float* __restrict__ bias, float* __restrict__ C)
{
    __shared__ __align__(16) uint32_t As[2][128][GST];   // 20KB
    __shared__ __align__(16) uint32_t Bs[2][128][GST];   // 20KB

    const int m0  = blockIdx.y * 128;
    const int n0  = blockIdx.x * 128;
    const int tid = threadIdx.x;        // 0..127
    const int lane = tid & 31;
    const int warp = tid >> 5;          // 0..3
    const int wm0 = (warp >> 1) * 64;   // 0 or 64
    const int wn0 = (warp & 1) * 64;    // 0 or 64
    const int r   = lane >> 2;          // 0..7
    const int cq  = lane & 3;           // 0..3

    const int lr  = tid >> 2;           // 0..31: staging rows lr+32j
    const int lc  = (tid & 3) << 2;     // k-chunk {0,4,8,12}

    const float* Ap = A + (size_t)(m0 + lr) * 512 + lc;
    const float* Wp = W + (size_t)(n0 + lr) * 512 + lc;

    float acc[4][8][4];
    #pragma unroll
    for (int mt = 0; mt < 4; mt++)
        #pragma unroll
        for (int nt = 0; nt < 8; nt++)
            #pragma unroll
            for (int i = 0; i < 4; i++) acc[mt][nt][i] = 0.f;

    float4 pa[4], pw[4];

    // ---- prologue: load + stage slab 0 into buffer 0 ----
    #pragma unroll
    for (int j = 0; j < 4; j++) {
        pa[j] = *(const float4*)(Ap + (size_t)(32 * j) * 512);
        pw[j] = *(const float4*)(Wp + (size_t)(32 * j) * 512);
    }
    #pragma unroll
    for (int j = 0; j < 4; j++) {
        *(uint4*)&As[0][lr + 32 * j][lc] =
            make_uint4(f32_tf32(pa[j].x), f32_tf32(pa[j].y), f32_tf32(pa[j].z), f32_tf32(pa[j].w));
        *(uint4*)&Bs[0][lr + 32 * j][lc] =
            make_uint4(f32_tf32(pw[j].x), f32_tf32(pw[j].y), f32_tf32(pw[j].z), f32_tf32(pw[j].w));
    }
    __syncthreads();

    #pragma unroll 2
    for (int k0 = 0; k0 < 512; k0 += 16) {
        const int buf = (k0 >> 4) & 1;
        const bool has_next = (k0 + 16) < 512;

        // prefetch next slab (latency covered by the MMA block below)
        if (has_next) {
            #pragma unroll
            for (int j = 0; j < 4; j++) {
                pa[j] = *(const float4*)(Ap + (size_t)(32 * j) * 512 + k0 + 16);
                pw[j] = *(const float4*)(Wp + (size_t)(32 * j) * 512 + k0 + 16);
            }
        }

        // ---- compute slab k0 from buffer buf ----
        #pragma unroll
        for (int ks = 0; ks < 2; ks++) {
            const int kb = ks * 8;
            uint32_t af[4][4];
            #pragma unroll
            for (int mt = 0; mt < 4; mt++) {
                const int mb = wm0 + mt * 16;
                af[mt][0] = As[buf][mb + r]    [kb + cq];
                af[mt][1] = As[buf][mb + r + 8][kb + cq];
                af[mt][2] = As[buf][mb + r]    [kb + cq + 4];
                af[mt][3] = As[buf][mb + r + 8][kb + cq + 4];
            }
            uint32_t bf[8][2];
            #pragma unroll
            for (int nt = 0; nt < 8; nt++) {
                const int nb = wn0 + nt * 8;
                bf[nt][0] = Bs[buf][nb + r][kb + cq];
                bf[nt][1] = Bs[buf][nb + r][kb + cq + 4];
            }
            #pragma unroll
            for (int mt = 0; mt < 4; mt++)
                #pragma unroll
                for (int nt = 0; nt < 8; nt++)
                    mma_tf32(acc[mt][nt], af[mt][0], af[mt][1], af[mt][2], af[mt][3],
                             bf[nt][0], bf[nt][1]);
        }

        // ---- stage prefetched slab into the other buffer ----
        if (has_next) {
            const int nb = buf ^ 1;
            #pragma unroll
            for (int j = 0; j < 4; j++) {
                *(uint4*)&As[nb][lr + 32 * j][lc] =
                    make_uint4(f32_tf32(pa[j].x), f32_tf32(pa[j].y), f32_tf32(pa[j].z), f32_tf32(pa[j].w));
                *(uint4*)&Bs[nb][lr + 32 * j][lc] =
                    make_uint4(f32_tf32(pw[j].x), f32_tf32(pw[j].y), f32_tf32(pw[j].z), f32_tf32(pw[j].w));
            }
        }
        __syncthreads();
    }

    #pragma unroll
    for (int nt = 0; nt < 8; nt++) {
        const int n = n0 + wn0 + nt * 8 + 2 * cq;
        const float2 bv = *(const float2*)(bias + n);
        #pragma unroll
        for (int mt = 0; mt < 4; mt++) {
            const int row = m0 + wm0 + mt * 16 + r;
            float2 o0, o1;
            o0.x = acc[mt][nt][0] + bv.x; o0.y = acc[mt][nt][1] + bv.y;
            o1.x = acc[mt][nt][2] + bv.x; o1.y = acc[mt][nt][3] + bv.y;
            *(float2*)(C + (size_t)row * 512 + n)       = o0;
            *(float2*)(C + (size_t)(row + 8) * 512 + n) = o1;
        }
    }
}

__global__ __launch_bounds__(128, 2) void qkv_gemm(
    const float* __restrict__ A,
    const float* __restrict__ Wq, const float* __restrict__ bq,
    const float* __restrict__ Wk, const float* __restrict__ bk,
    const float* __restrict__ Wv, const float* __restrict__ bv,
    float* __restrict__ Cq, float* __restrict__ Ck, float* __restrict__ Cv)
{
    const int z = blockIdx.z;
    const float* W    = (z == 0) ? Wq : (z == 1) ? Wk : Wv;
    const float* bias = (z == 0) ? bq : (z == 1) ? bk : bv;
    float*       C    = (z == 0) ? Cq : (z == 1) ? Ck : Cv;
    gemm_tf32_body(A, W, bias, C);
}

__global__ __launch_bounds__(128, 2) void out_gemm(
    const float* __restrict__ A, const float* __restrict__ W,
    const float* __restrict__ bias, float* __restrict__ C)
{
    gemm_tf32_body(A, W, bias, C);
}

// ============================================================================
// Tensor-core flash attention, 128-query tile, register-resident P.
// (unchanged from passing round 13)
// ============================================================================
#define KS_STR 68
#define VS_STR 72

__global__ __launch_bounds__(256, 2) void attn_tc(
    const float* __restrict__ Q, const float* __restrict__ Kg,
    const float* __restrict__ Vg,
    const float* __restrict__ rel,           // [1023, 8]
    const unsigned int* __restrict__ kpm,    // [B, T], nonzero word => masked
    float* __restrict__ out)                 // [B, T, H, DK]
{
    __shared__ __align__(16) float Ks[64 * KS_STR];
    __shared__ __align__(16) float Vs[64 * VS_STR];
    __shared__ float bias_s[192];
    __shared__ float mask_s[64];

    const int bh = blockIdx.y;
    const int b  = bh >> 3;
    const int h  = bh & 7;
    const int q0 = blockIdx.x * 128;
    const int tid  = threadIdx.x;
    const int lane = tid & 31;
    const int warp = tid >> 5;
    const int r  = lane >> 2;
    const int cq = lane & 3;
    const int wm = warp * 16;

    const int sr = tid >> 2;
    const int sc = (tid & 3) * 16;

    const float* qg = Q + ((size_t)(b * T_ + q0)) * D_ + h * DK_;
    uint32_t qf[8][4];
    #pragma unroll
    for (int ks = 0; ks < 8; ks++) {
        qf[ks][0] = f32_tf32(qg[(size_t)(wm + r)     * D_ + ks * 8 + cq]);
        qf[ks][1] = f32_tf32(qg[(size_t)(wm + r + 8) * D_ + ks * 8 + cq]);
        qf[ks][2] = f32_tf32(qg[(size_t)(wm + r)     * D_ + ks * 8 + cq + 4]);
        qf[ks][3] = f32_tf32(qg[(size_t)(wm + r + 8) * D_ + ks * 8 + cq + 4]);
    }

    float m0 = -1e30f, m1 = -1e30f, l0 = 0.f, l1 = 0.f;
    float oacc[8][4];
    #pragma unroll
    for (int nt = 0; nt < 8; nt++)
        #pragma unroll
        for (int i = 0; i < 4; i++) oacc[nt][i] = 0.f;

    const int srcA = (lane & ~3) | (cq >> 1);
    const int srcB = srcA + 2;
    const bool odd = (cq & 1);

    for (int kt = 0; kt < 8; kt++) {
        const int k0 = kt * 64;
        __syncthreads();

        const float* kg = Kg + ((size_t)(b * T_ + k0)) * D_ + h * DK_;
        const float* vg = Vg + ((size_t)(b * T_ + k0)) * D_ + h * DK_;
        #pragma unroll
        for (int c = 0; c < 4; c++) {
            float4 kv = *(const float4*)(kg + (size_t)sr * D_ + sc + c * 4);
            float4 kt4;
            kt4.x = tf32f(kv.x); kt4.y = tf32f(kv.y);
            kt4.z = tf32f(kv.z); kt4.w = tf32f(kv.w);
            *(float4*)&Ks[sr * KS_STR + sc + c * 4] = kt4;
            float4 vv = *(const float4*)(vg + (size_t)sr * D_ + sc + c * 4);
            float4 vt4;
            vt4.x = tf32f(vv.x); vt4.y = tf32f(vv.y);
            vt4.z = tf32f(vv.z); vt4.w = tf32f(vv.w);
            *(float4*)&Vs[sr * VS_STR + sc + c * 4] = vt4;
        }
        if (tid < 191)
            bias_s[tid] = __ldg(&rel[(k0 - q0 - 127 + tid + 511) * 8 + h]);
        if (tid < 64)
            mask_s[tid] = __ldg(&kpm[b * T_ + k0 + tid]) ? -2e30f : 0.f;
        __syncthreads();

        float sacc[8][4];
        #pragma unroll
        for (int nt = 0; nt < 8; nt++)
            #pragma unroll
            for (int i = 0; i < 4; i++) sacc[nt][i] = 0.f;

        #pragma unroll
        for (int ks = 0; ks < 8; ks++) {
            #pragma unroll
            for (int nt = 0; nt < 8; nt++) {
                uint32_t b0 = __float_as_uint(Ks[(nt * 8 + r) * KS_STR + ks * 8 + cq]);
                uint32_t b1 = __float_as_uint(Ks[(nt * 8 + r) * KS_STR + ks * 8 + cq + 4]);
                mma_tf32(sacc[nt], qf[ks][0], qf[ks][1], qf[ks][2], qf[ks][3], b0, b1);
            }
        }

        const int rr0 = wm + r, rr1 = wm + r + 8;
        #pragma unroll
        for (int nt = 0; nt < 8; nt++) {
            const int cc = nt * 8 + 2 * cq;
            const float mk0 = mask_s[cc], mk1 = mask_s[cc + 1];
            sacc[nt][0] = fmaf(sacc[nt][0], 0.125f, bias_s[cc     - rr0 + 127] + mk0);
            sacc[nt][1] = fmaf(sacc[nt][1], 0.125f, bias_s[cc + 1 - rr0 + 127] + mk1);
            sacc[nt][2] = fmaf(sacc[nt][2], 0.125f, bias_s[cc     - rr1 + 127] + mk0);
            sacc[nt][3] = fmaf(sacc[nt][3], 0.125f, bias_s[cc + 1 - rr1 + 127] + mk1);
        }

        float rm0 = -1e30f, rm1 = -1e30f;
        #pragma unroll
        for (int nt = 0; nt < 8; nt++) {
            rm0 = fmaxf(rm0, fmaxf(sacc[nt][0], sacc[nt][1]));
            rm1 = fmaxf(rm1, fmaxf(sacc[nt][2], sacc[nt][3]));
        }
        rm0 = fmaxf(rm0, __shfl_xor_sync(0xffffffffu, rm0, 1));
        rm0 = fmaxf(rm0, __shfl_xor_sync(0xffffffffu, rm0, 2));
        rm1 = fmaxf(rm1, __shfl_xor_sync(0xffffffffu, rm1, 1));
        rm1 = fmaxf(rm1, __shfl_xor_sync(0xffffffffu, rm1, 2));

        const float mn0 = fmaxf(m0, rm0), mn1 = fmaxf(m1, rm1);
        const float al0 = __expf(m0 - mn0), al1 = __expf(m1 - mn1);
        m0 = mn0; m1 = mn1;

        float rs0 = 0.f, rs1 = 0.f;
        #pragma unroll
        for (int nt = 0; nt < 8; nt++) {
            sacc[nt][0] = __expf(sacc[nt][0] - mn0);
            sacc[nt][1] = __expf(sacc[nt][1] - mn0);
            sacc[nt][2] = __expf(sacc[nt][2] - mn1);
            sacc[nt][3] = __expf(sacc[nt][3] - mn1);
            rs0 += sacc[nt][0] + sacc[nt][1];
            rs1 += sacc[nt][2] + sacc[nt][3];
        }
        rs0 += __shfl_xor_sync(0xffffffffu, rs0, 1);
        rs0 += __shfl_xor_sync(0xffffffffu, rs0, 2);
        rs1 += __shfl_xor_sync(0xffffffffu, rs1, 1);
        rs1 += __shfl_xor_sync(0xffffffffu, rs1, 2);
        l0 = l0 * al0 + rs0;
        l1 = l1 * al1 + rs1;
        #pragma unroll
        for (int nt = 0; nt < 8; nt++) {
            oacc[nt][0] *= al0; oacc[nt][1] *= al0;
            oacc[nt][2] *= al1; oacc[nt][3] *= al1;
            sacc[nt][0] = tf32f(sacc[nt][0]);
            sacc[nt][1] = tf32f(sacc[nt][1]);
            sacc[nt][2] = tf32f(sacc[nt][2]);
            sacc[nt][3] = tf32f(sacc[nt][3]);
        }

        #pragma unroll
        for (int ks = 0; ks < 8; ks++) {
            float vA0 = __shfl_sync(0xffffffffu, sacc[ks][0], srcA);
            float vA1 = __shfl_sync(0xffffffffu, sacc[ks][1], srcA);
            float vA2 = __shfl_sync(0xffffffffu, sacc[ks][2], srcA);
            float vA3 = __shfl_sync(0xffffffffu, sacc[ks][3], srcA);
            float vB0 = __shfl_sync(0xffffffffu, sacc[ks][0], srcB);
            float vB1 = __shfl_sync(0xffffffffu, sacc[ks][1], srcB);
            float vB2 = __shfl_sync(0xffffffffu, sacc[ks][2], srcB);
            float vB3 = __shfl_sync(0xffffffffu, sacc[ks][3], srcB);
            uint32_t a0 = __float_as_uint(odd ? vA1 : vA0);
            uint32_t a1 = __float_as_uint(odd ? vA3 : vA2);
            uint32_t a2 = __float_as_uint(odd ? vB1 : vB0);
            uint32_t a3 = __float_as_uint(odd ? vB3 : vB2);
            #pragma unroll
            for (int nt = 0; nt < 8; nt++) {
                uint32_t b0 = __float_as_uint(Vs[(ks * 8 + cq)     * VS_STR + nt * 8 + r]);
                uint32_t b1 = __float_as_uint(Vs[(ks * 8 + cq + 4) * VS_STR + nt * 8 + r]);
                mma_tf32(oacc[nt], a0, a1, a2, a3, b0, b1);
            }
        }
    }

    const float inv0 = 1.f / l0, inv1 = 1.f / l1;
    const int row0 = b * T_ + q0 + wm + r;
    #pragma unroll
    for (int nt = 0; nt < 8; nt++) {
        const int col = h * DK_ + nt * 8 + 2 * cq;
        float2 o0, o1;
        o0.x = oacc[nt][0] * inv0; o0.y = oacc[nt][1] * inv0;
        o1.x = oacc[nt][2] * inv1; o1.y = oacc[nt][3] * inv1;
        *(float2*)(out + (size_t)row0 * D_ + col)       = o0;
        *(float2*)(out + (size_t)(row0 + 8) * D_ + col) = o1;
    }
}

// ============================================================================
extern "C" void kernel_launch(void* const* d_in, const int* in_sizes, int n_in,
                              void* d_out, int out_size)
{
    const float* x   = (const float*)d_in[0];
    const float* Wq  = (const float*)d_in[1];
    const float* bq  = (const float*)d_in[2];
    const float* Wk  = (const float*)d_in[3];
    const float* bk  = (const float*)d_in[4];
    const float* Wv  = (const float*)d_in[5];
    const float* bv  = (const float*)d_in[6];
    const float* Wo  = (const float*)d_in[7];
    const float* bo  = (const float*)d_in[8];
    const float* rel = (const float*)d_in[9];
    const unsigned int* kpm = (const unsigned int*)d_in[10];
    float* out = (float*)d_out;

    float *qp, *kp, *vp, *ap;
    cudaGetSymbolAddress((void**)&qp, g_q);
    cudaGetSymbolAddress((void**)&kp, g_k);
    cudaGetSymbolAddress((void**)&vp, g_v);
    cudaGetSymbolAddress((void**)&ap, g_att);

    dim3 qkv_grid(D_ / 128, M_ / 128, 3);   // (4, 128, 3)
    qkv_gemm<<<qkv_grid, 128>>>(x, Wq, bq, Wk, bk, Wv, bv, qp, kp, vp);

    dim3 at_grid(T_ / 128, B_ * H_);        // (4, 256)
    attn_tc<<<at_grid, 256>>>(qp, kp, vp, rel, kpm, ap);

    dim3 gemm_grid(D_ / 128, M_ / 128);     // (4, 128)
    out_gemm<<<gemm_grid, 128>>>(ap, Wo, bo, out);
}